// round 12
// baseline (speedup 1.0000x reference)
#include <cuda_runtime.h>
#include <cuda_bf16.h>
#include <math.h>
#include <stdint.h>

// Problem constants
#define BB  2
#define NN  2048
#define MM  1024
#define LL  3072   // NN + MM
#define DD  1024
#define HH  16
#define DHH 64

#define SCALE_Q 0.18033688011112042f   // 0.125 * log2(e): softmax in exp2 domain

// ---------------------------------------------------------------------------
// Scratch (allocation-free rule: __device__ globals)
// K kept as bf16-hi ONLY (q·klo residual measured at ~6e-4 final rel err).
// ---------------------------------------------------------------------------
__device__ __align__(16) __nv_bfloat16 g_qhi[BB*HH*NN*DHH], g_qlo[BB*HH*NN*DHH];
__device__ __align__(16) __nv_bfloat16 g_khi[BB*HH*LL*DHH];
__device__ __align__(16) __nv_bfloat16 g_vhi[BB*HH*LL*DHH], g_vlo[BB*HH*LL*DHH];

__device__ __align__(16) __nv_bfloat16 g_xhi [BB*NN*DD], g_xlo [BB*NN*DD];
__device__ __align__(16) __nv_bfloat16 g_chi [BB*MM*DD], g_clo [BB*MM*DD];
__device__ __align__(16) __nv_bfloat16 g_wqt_hi [DD*DD],   g_wqt_lo [DD*DD];   // [n][k]
__device__ __align__(16) __nv_bfloat16 g_wkvt_hi[2*DD*DD], g_wkvt_lo[2*DD*DD]; // [n][k]
__device__ __align__(16) __nv_bfloat16 g_wot_hi [DD*DD],   g_wot_lo [DD*DD];   // [n][k]
__device__ __align__(16) __nv_bfloat16 g_aohi[BB*NN*DD], g_aolo[BB*NN*DD];

// ---------------------------------------------------------------------------
// Helpers
// ---------------------------------------------------------------------------
__device__ __forceinline__ uint32_t s2u(const void* p){
    uint32_t a;
    asm("{ .reg .u64 t; cvta.to.shared.u64 t, %1; cvt.u32.u64 %0, t; }" : "=r"(a) : "l"(p));
    return a;
}
__device__ __forceinline__ uint32_t bpack(__nv_bfloat16 a, __nv_bfloat16 b){
    return (uint32_t)__bfloat16_as_ushort(a) | ((uint32_t)__bfloat16_as_ushort(b) << 16);
}
__device__ __forceinline__ void cp16(uint32_t s, const void* g){
    asm volatile("cp.async.cg.shared.global [%0], [%1], 16;" :: "r"(s), "l"(g));
}
#define CP_COMMIT() asm volatile("cp.async.commit_group;")

__device__ __forceinline__ float ex2(float x){
    float y; asm("ex2.approx.f32 %0, %1;" : "=f"(y) : "f"(x)); return y;
}

#define MMA_BF16(C, A, b0, b1) \
    asm volatile("mma.sync.aligned.m16n8k16.row.col.f32.bf16.bf16.f32 " \
        "{%0,%1,%2,%3}, {%4,%5,%6,%7}, {%8,%9}, {%0,%1,%2,%3};" \
        : "+f"((C)[0]), "+f"((C)[1]), "+f"((C)[2]), "+f"((C)[3]) \
        : "r"((A)[0]), "r"((A)[1]), "r"((A)[2]), "r"((A)[3]), "r"(b0), "r"(b1))

#define LDSM4(r, addr) \
    asm volatile("ldmatrix.sync.aligned.m8n8.x4.shared.b16 {%0,%1,%2,%3}, [%4];" \
        : "=r"((r)[0]), "=r"((r)[1]), "=r"((r)[2]), "=r"((r)[3]) : "r"(addr))

#define LDSM4T(r0,r1,r2,r3,addr) \
    asm volatile("ldmatrix.sync.aligned.m8n8.x4.trans.shared.b16 {%0,%1,%2,%3}, [%4];" \
        : "=r"(r0), "=r"(r1), "=r"(r2), "=r"(r3) : "r"(addr))

__device__ __forceinline__ void split2(float x, float y, uint32_t& hi, uint32_t& lo){
    __nv_bfloat16 h0 = __float2bfloat16_rn(x), h1 = __float2bfloat16_rn(y);
    hi = bpack(h0, h1);
    lo = bpack(__float2bfloat16_rn(x - __bfloat162float(h0)),
               __float2bfloat16_rn(y - __bfloat162float(h1)));
}

// ---------------------------------------------------------------------------
// Prep: ONE kernel — splits x/context AND transposes+splits all weights.
// ---------------------------------------------------------------------------
#define NX4 (BB*NN*DD/4)
#define NC4 (BB*MM*DD/4)
#define NSPLIT_BLK ((NX4 + NC4) / 256)        // 6144
#define NTRANS_BLK (128 * 32)                 // 4096

__global__ __launch_bounds__(256) void prep_all(
    const float4* __restrict__ x, const float4* __restrict__ ctx,
    const float* __restrict__ Wq, const float* __restrict__ Wkv,
    const float* __restrict__ Wo)
{
    int bid = blockIdx.x;
    if (bid < NSPLIT_BLK){
        int i = bid * 256 + threadIdx.x;
        const float4* src;  uint2 *hi, *lo;  int j;
        if (i < NX4){ src = x;   hi = (uint2*)g_xhi; lo = (uint2*)g_xlo; j = i; }
        else        { src = ctx; hi = (uint2*)g_chi; lo = (uint2*)g_clo; j = i - NX4; }
        float4 v = src[j];
        uint32_t h0, l0, h1, l1;
        split2(v.x, v.y, h0, l0);
        split2(v.z, v.w, h1, l1);
        hi[j] = make_uint2(h0, h1);
        lo[j] = make_uint2(l0, l1);
        return;
    }
    int id = bid - NSPLIT_BLK;
    int cx = id & 127, ky = id >> 7;
    const float* W; __nv_bfloat16 *th, *tl; int N, n0;
    if (cx < 32){       W = Wq;  N = 1024; n0 = cx*32;      th = g_wqt_hi;  tl = g_wqt_lo;  }
    else if (cx < 96){  W = Wkv; N = 2048; n0 = (cx-32)*32; th = g_wkvt_hi; tl = g_wkvt_lo; }
    else{               W = Wo;  N = 1024; n0 = (cx-96)*32; th = g_wot_hi;  tl = g_wot_lo;  }

    __shared__ float t[32][33];
    int k0 = ky * 32;
    int tx = threadIdx.x & 31, ty = threadIdx.x >> 5;
    #pragma unroll
    for (int r = 0; r < 4; r++)
        t[ty + r*8][tx] = W[(size_t)(k0 + ty + r*8) * N + n0 + tx];
    __syncthreads();
    #pragma unroll
    for (int r = 0; r < 4; r++){
        int n = ty + r*8;
        float v = t[tx][n];
        __nv_bfloat16 h = __float2bfloat16_rn(v);
        __nv_bfloat16 l = __float2bfloat16_rn(v - __bfloat162float(h));
        size_t o = (size_t)(n0 + n) * 1024 + k0 + tx;
        th[o] = h; tl[o] = l;
    }
}

// ---------------------------------------------------------------------------
// GEMM: 128x128 CTA tile, BK=16, FOUR-stage cp.async pipeline (depth-3
// prefetch, constant-pending wait_group 2), one __syncthreads per iter.
// Fragment/warp-tile layout identical to the proven round-7 kernel.
// ---------------------------------------------------------------------------
#define PITCH 48                    // 32B data (16 bf16) + 16B pad, 16B-aligned
#define MATB  (128*PITCH)           // 6144 B
#define STAGEB (4*MATB)             // 24576 B (Ahi, Alo, Bhi, Blo)
#define NSTAGE 4
#define GEMM_SMEM (NSTAGE*STAGEB)   // 98304 B

// Fused Q + KV projection: 1024 CTAs. cid<256 -> Q tile; else KV tile.
__global__ __launch_bounds__(256, 2) void gemm_qkv(const float* __restrict__ bq,
                                                   const float* __restrict__ bkv)
{
    extern __shared__ char sm[];
    const int tid  = threadIdx.x;
    const int lane = tid & 31;
    const int warp = tid >> 5;
    const int wM = warp & 3, wN = warp >> 2;
    const int g  = lane >> 2, t = lane & 3;

    const int cid = blockIdx.x;
    const bool isQ = (cid < 256);
    int rowBase, colBase;
    const __nv_bfloat16 *Bh, *Bl;
    const float* bias;
    if (isQ){
        rowBase = (cid >> 3) * 128;  colBase = (cid & 7) * 128;
        Bh = g_wqt_hi;  Bl = g_wqt_lo;  bias = bq;
    } else {
        int c2 = cid - 256;
        rowBase = (c2 >> 4) * 128;   colBase = (c2 & 15) * 128;
        Bh = g_wkvt_hi; Bl = g_wkvt_lo; bias = bkv;
    }

    // loader: thread -> (row, 16B-chunk): 128 rows x 2 chunks = 256 threads
    const int      lr  = tid >> 1;
    const uint32_t lcb = (tid & 1) * 16;
    const char *pAh, *pAl, *pBh, *pBl;
    {
        int row = rowBase + lr;
        const __nv_bfloat16 *ah, *al; size_t ro;
        if (isQ){
            ah = g_xhi;  al = g_xlo;  ro = (size_t)row * DD;
        } else {
            int b = row / LL, jj = row % LL;
            if (jj < NN){ ah = g_xhi; al = g_xlo; ro = (size_t)(b*NN + jj) * DD; }
            else        { ah = g_chi; al = g_clo; ro = (size_t)(b*MM + jj - NN) * DD; }
        }
        pAh = (const char*)(ah + ro);
        pAl = (const char*)(al + ro);
        size_t bo = (size_t)(colBase + lr) * DD;
        pBh = (const char*)(Bh + bo);
        pBl = (const char*)(Bl + bo);
    }

    const uint32_t smBase = s2u(sm);
    auto load_stage = [&](int it){
        uint32_t sb = smBase + (it & 3) * STAGEB;
        uint32_t so = lr * PITCH + lcb;
        uint32_t go = it * 32 + lcb;         // 16 bf16 = 32 B per iter per row
        cp16(sb + so,          pAh + go);
        cp16(sb + MATB + so,   pAl + go);
        cp16(sb + 2*MATB + so, pBh + go);
        cp16(sb + 3*MATB + so, pBl + go);
        CP_COMMIT();
    };

    float c[2][8][4];
    #pragma unroll
    for (int mt = 0; mt < 2; mt++)
        #pragma unroll
        for (int nt = 0; nt < 8; nt++)
            #pragma unroll
            for (int i = 0; i < 4; i++) c[mt][nt][i] = 0.f;

    const uint32_t aRow = (lane & 7) + ((lane >> 3) & 1) * 8;
    const uint32_t aK   = ((lane >> 4) & 1) * 16;
    const uint32_t bRow = (lane & 7) + ((lane >> 4) & 1) * 8;
    const uint32_t bK   = ((lane >> 3) & 1) * 16;

    load_stage(0); load_stage(1); load_stage(2);

    for (int it = 0; it < 64; ++it){
        asm volatile("cp.async.wait_group 2;" ::: "memory");
        __syncthreads();
        if (it + 3 < 64) load_stage(it + 3);
        else             CP_COMMIT();        // keep pending count constant

        const uint32_t sbu = smBase + (it & 3) * STAGEB;
        uint32_t a0[2][4], a1[2][4];
        #pragma unroll
        for (int mt = 0; mt < 2; mt++){
            LDSM4(a0[mt], sbu + (wM*32 + mt*16 + aRow)*PITCH + aK);
            LDSM4(a1[mt], sbu + MATB + (wM*32 + mt*16 + aRow)*PITCH + aK);
        }
        #pragma unroll
        for (int ntp = 0; ntp < 4; ntp++){
            uint32_t bh[4], bl[4];
            uint32_t bro = (wN*64 + ntp*16 + bRow)*PITCH + bK;
            LDSM4(bh, sbu + 2*MATB + bro);
            LDSM4(bl, sbu + 3*MATB + bro);
            #pragma unroll
            for (int hf = 0; hf < 2; hf++)
                #pragma unroll
                for (int mt = 0; mt < 2; mt++)
                    MMA_BF16(c[mt][ntp*2+hf], a0[mt], bh[hf*2], bh[hf*2+1]);
            #pragma unroll
            for (int hf = 0; hf < 2; hf++)
                #pragma unroll
                for (int mt = 0; mt < 2; mt++)
                    MMA_BF16(c[mt][ntp*2+hf], a0[mt], bl[hf*2], bl[hf*2+1]);
            #pragma unroll
            for (int hf = 0; hf < 2; hf++)
                #pragma unroll
                for (int mt = 0; mt < 2; mt++)
                    MMA_BF16(c[mt][ntp*2+hf], a1[mt], bh[hf*2], bh[hf*2+1]);
        }
    }

    // --- epilogue ---
    #pragma unroll
    for (int mt = 0; mt < 2; mt++){
        int row0 = rowBase + wM*32 + mt*16 + g;
        #pragma unroll
        for (int nt = 0; nt < 8; nt++){
            int col = colBase + wN*64 + nt*8 + t*2;
            float2 bz = *(const float2*)(bias + col);
            #pragma unroll
            for (int hrow = 0; hrow < 2; hrow++){
                int row = row0 + hrow*8;
                float vx = c[mt][nt][hrow*2]   + bz.x;
                float vy = c[mt][nt][hrow*2+1] + bz.y;
                if (isQ){
                    int b = row / NN, qi = row % NN;
                    int hh = col >> 6, d2 = col & 63;
                    uint32_t hi, lo;
                    split2(vx * SCALE_Q, vy * SCALE_Q, hi, lo);
                    size_t o = ((size_t)(b*HH + hh) * NN + qi) * DHH + d2;
                    *(uint32_t*)&g_qhi[o] = hi;
                    *(uint32_t*)&g_qlo[o] = lo;
                } else {
                    int b = row / LL, jj = row % LL;
                    if (col < DD){
                        int hh = col >> 6, d2 = col & 63;
                        size_t o = ((size_t)(b*HH + hh) * LL + jj) * DHH + d2;
                        *(uint32_t*)&g_khi[o] =
                            bpack(__float2bfloat16_rn(vx), __float2bfloat16_rn(vy));
                    } else {
                        int c2 = col - DD;
                        int hh = c2 >> 6, d2 = c2 & 63;
                        uint32_t hi, lo;
                        split2(vx, vy, hi, lo);
                        size_t o = ((size_t)(b*HH + hh) * LL + jj) * DHH + d2;
                        *(uint32_t*)&g_vhi[o] = hi;
                        *(uint32_t*)&g_vlo[o] = lo;
                    }
                }
            }
        }
    }
}

// O-projection: out = ao @ Wo + bo  (same 4-stage BK=16 pipeline)
__global__ __launch_bounds__(256, 2) void gemm_o(const float* __restrict__ bias,
                                                 float* __restrict__ out)
{
    extern __shared__ char sm[];
    const int tid  = threadIdx.x;
    const int lane = tid & 31;
    const int warp = tid >> 5;
    const int wM = warp & 3, wN = warp >> 2;
    const int g  = lane >> 2, t = lane & 3;

    const int rowBase = blockIdx.y * 128;
    const int colBase = blockIdx.x * 128;

    const int      lr  = tid >> 1;
    const uint32_t lcb = (tid & 1) * 16;
    const char* pAh = (const char*)(g_aohi + (size_t)(rowBase + lr) * DD);
    const char* pAl = (const char*)(g_aolo + (size_t)(rowBase + lr) * DD);
    const char* pBh = (const char*)(g_wot_hi + (size_t)(colBase + lr) * DD);
    const char* pBl = (const char*)(g_wot_lo + (size_t)(colBase + lr) * DD);

    const uint32_t smBase = s2u(sm);
    auto load_stage = [&](int it){
        uint32_t sb = smBase + (it & 3) * STAGEB;
        uint32_t so = lr * PITCH + lcb;
        uint32_t go = it * 32 + lcb;
        cp16(sb + so,          pAh + go);
        cp16(sb + MATB + so,   pAl + go);
        cp16(sb + 2*MATB + so, pBh + go);
        cp16(sb + 3*MATB + so, pBl + go);
        CP_COMMIT();
    };

    float c[2][8][4];
    #pragma unroll
    for (int mt = 0; mt < 2; mt++)
        #pragma unroll
        for (int nt = 0; nt < 8; nt++)
            #pragma unroll
            for (int i = 0; i < 4; i++) c[mt][nt][i] = 0.f;

    const uint32_t aRow = (lane & 7) + ((lane >> 3) & 1) * 8;
    const uint32_t aK   = ((lane >> 4) & 1) * 16;
    const uint32_t bRow = (lane & 7) + ((lane >> 4) & 1) * 8;
    const uint32_t bK   = ((lane >> 3) & 1) * 16;

    load_stage(0); load_stage(1); load_stage(2);

    for (int it = 0; it < 64; ++it){
        asm volatile("cp.async.wait_group 2;" ::: "memory");
        __syncthreads();
        if (it + 3 < 64) load_stage(it + 3);
        else             CP_COMMIT();

        const uint32_t sbu = smBase + (it & 3) * STAGEB;
        uint32_t a0[2][4], a1[2][4];
        #pragma unroll
        for (int mt = 0; mt < 2; mt++){
            LDSM4(a0[mt], sbu + (wM*32 + mt*16 + aRow)*PITCH + aK);
            LDSM4(a1[mt], sbu + MATB + (wM*32 + mt*16 + aRow)*PITCH + aK);
        }
        #pragma unroll
        for (int ntp = 0; ntp < 4; ntp++){
            uint32_t bh[4], bl[4];
            uint32_t bro = (wN*64 + ntp*16 + bRow)*PITCH + bK;
            LDSM4(bh, sbu + 2*MATB + bro);
            LDSM4(bl, sbu + 3*MATB + bro);
            #pragma unroll
            for (int hf = 0; hf < 2; hf++)
                #pragma unroll
                for (int mt = 0; mt < 2; mt++)
                    MMA_BF16(c[mt][ntp*2+hf], a0[mt], bh[hf*2], bh[hf*2+1]);
            #pragma unroll
            for (int hf = 0; hf < 2; hf++)
                #pragma unroll
                for (int mt = 0; mt < 2; mt++)
                    MMA_BF16(c[mt][ntp*2+hf], a0[mt], bl[hf*2], bl[hf*2+1]);
            #pragma unroll
            for (int hf = 0; hf < 2; hf++)
                #pragma unroll
                for (int mt = 0; mt < 2; mt++)
                    MMA_BF16(c[mt][ntp*2+hf], a1[mt], bh[hf*2], bh[hf*2+1]);
        }
    }

    #pragma unroll
    for (int mt = 0; mt < 2; mt++){
        int row0 = rowBase + wM*32 + mt*16 + g;
        #pragma unroll
        for (int nt = 0; nt < 8; nt++){
            int col = colBase + wN*64 + nt*8 + t*2;
            float2 bz = *(const float2*)(bias + col);
            #pragma unroll
            for (int hrow = 0; hrow < 2; hrow++){
                int row = row0 + hrow*8;
                *(float2*)&out[(size_t)row * DD + col] =
                    make_float2(c[mt][nt][hrow*2] + bz.x, c[mt][nt][hrow*2+1] + bz.y);
            }
        }
    }
}

// ---------------------------------------------------------------------------
// HMMA flash attention (round-10 structure, reverted): 128 q/CTA, 8 warps,
// 64-key tiles, K bf16-hi only, PV 3-term split, ex2 softmax, heavy-first.
// ---------------------------------------------------------------------------
#define KROW    144
#define KVMAT   (64*KROW)
#define KVSTAGE (3*KVMAT)            // Khi, Vhi, Vlo = 27648 B
#define FA_SMEM (2*KVSTAGE)          // 55296 B

__global__ __launch_bounds__(256, 2) void flash_mma()
{
    extern __shared__ char fsm[];
    const int tid = threadIdx.x, lane = tid & 31, warp = tid >> 5;
    const int g = lane >> 2, t = lane & 3;
    const int q0 = (int)(gridDim.x - 1 - blockIdx.x) * 128;   // heavy-first
    const int h  = blockIdx.y;
    const int b  = blockIdx.z;

    const __nv_bfloat16* qh = g_qhi + ((size_t)(b*HH + h) * NN + q0 + warp*16) * DHH;
    const __nv_bfloat16* ql = g_qlo + ((size_t)(b*HH + h) * NN + q0 + warp*16) * DHH;
    uint32_t qa[2][4][4];
    #pragma unroll
    for (int kc = 0; kc < 4; kc++){
        int e0 = g*DHH + kc*16 + 2*t;
        qa[0][kc][0] = *(const uint32_t*)(qh + e0);
        qa[0][kc][1] = *(const uint32_t*)(qh + e0 + 8*DHH);
        qa[0][kc][2] = *(const uint32_t*)(qh + e0 + 8);
        qa[0][kc][3] = *(const uint32_t*)(qh + e0 + 8*DHH + 8);
        qa[1][kc][0] = *(const uint32_t*)(ql + e0);
        qa[1][kc][1] = *(const uint32_t*)(ql + e0 + 8*DHH);
        qa[1][kc][2] = *(const uint32_t*)(ql + e0 + 8);
        qa[1][kc][3] = *(const uint32_t*)(ql + e0 + 8*DHH + 8);
    }

    float o[8][4];
    #pragma unroll
    for (int nt = 0; nt < 8; nt++)
        #pragma unroll
        for (int i = 0; i < 4; i++) o[nt][i] = 0.f;
    float m2[2] = {-1e30f, -1e30f}, l2[2] = {0.f, 0.f};

    const size_t kvbase = (size_t)(b*HH + h) * LL;
    const int nSelf = q0/64 + 2;
    const int nBlk  = nSelf + MM/64;
    auto jof = [&](int blk){ return blk < nSelf ? blk*64 : NN + (blk - nSelf)*64; };

    const uint32_t fsb = s2u(fsm);
    auto load_kv = [&](int j0, int st){
        uint32_t sb = fsb + st * KVSTAGE;
        size_t go = (kvbase + j0) * DHH;
        #pragma unroll
        for (int i = 0; i < 2; i++){
            int idx = tid + i*256;          // 0..511 = 64 rows x 8 chunks
            int r = idx >> 3, cb = (idx & 7) * 16;
            uint32_t so = r*KROW + cb;
            size_t ge = go + (size_t)r*DHH + (cb >> 1);
            cp16(sb + so,           g_khi + ge);
            cp16(sb + KVMAT + so,   g_vhi + ge);
            cp16(sb + 2*KVMAT + so, g_vlo + ge);
        }
        CP_COMMIT();
    };

    const uint32_t kRowL = (lane & 7) + ((lane >> 4) & 1) * 8;
    const uint32_t kKL   = ((lane >> 3) & 1) * 16;
    const uint32_t rowad = (lane & 7)*KROW + ((lane >> 4) & 1)*16 +
                           (((lane >> 3) & 1) ? 8*KROW : 0);

    load_kv(0, 0);

    for (int blk = 0; blk < nBlk; ++blk){
        const int j0 = jof(blk);
        asm volatile("cp.async.wait_group 0;" ::: "memory");
        __syncthreads();
        if (blk + 1 < nBlk) load_kv(jof(blk + 1), (blk + 1) & 1);

        const uint32_t stU = fsb + (blk & 1) * KVSTAGE;
        const uint32_t KhU = stU;
        const uint32_t vhB = stU + KVMAT;
        const uint32_t vlB = stU + 2*KVMAT;

        // --- S = (qhi + qlo) · khi ---
        float s[8][4];
        #pragma unroll
        for (int nt = 0; nt < 8; nt++)
            s[nt][0] = s[nt][1] = s[nt][2] = s[nt][3] = 0.f;
        #pragma unroll
        for (int kc = 0; kc < 4; kc++){
            #pragma unroll
            for (int ntp = 0; ntp < 4; ntp++){
                uint32_t bh[4];
                LDSM4(bh, KhU + (ntp*16 + kRowL)*KROW + kc*32 + kKL);
                MMA_BF16(s[ntp*2],   qa[0][kc], bh[0], bh[1]);
                MMA_BF16(s[ntp*2+1], qa[0][kc], bh[2], bh[3]);
                MMA_BF16(s[ntp*2],   qa[1][kc], bh[0], bh[1]);
                MMA_BF16(s[ntp*2+1], qa[1][kc], bh[2], bh[3]);
            }
        }

        // --- causal mask (last two self tiles only) ---
        if (blk >= nSelf - 2 && blk < nSelf){
            int rA = q0 + warp*16 + g, rB = rA + 8;
            #pragma unroll
            for (int nt = 0; nt < 8; nt++){
                int k0 = j0 + nt*8 + 2*t;
                if (k0     > rA) s[nt][0] = -1e30f;
                if (k0 + 1 > rA) s[nt][1] = -1e30f;
                if (k0     > rB) s[nt][2] = -1e30f;
                if (k0 + 1 > rB) s[nt][3] = -1e30f;
            }
        }

        // --- online softmax (exp2 domain) ---
        float mxA = -1e30f, mxB = -1e30f;
        #pragma unroll
        for (int nt = 0; nt < 8; nt++){
            mxA = fmaxf(mxA, fmaxf(s[nt][0], s[nt][1]));
            mxB = fmaxf(mxB, fmaxf(s[nt][2], s[nt][3]));
        }
        mxA = fmaxf(mxA, __shfl_xor_sync(0xffffffffu, mxA, 1));
        mxA = fmaxf(mxA, __shfl_xor_sync(0xffffffffu, mxA, 2));
        mxB = fmaxf(mxB, __shfl_xor_sync(0xffffffffu, mxB, 1));
        mxB = fmaxf(mxB, __shfl_xor_sync(0xffffffffu, mxB, 2));

        float mnA = fmaxf(m2[0], mxA), mnB = fmaxf(m2[1], mxB);
        float aA = ex2(m2[0] - mnA), aB = ex2(m2[1] - mnB);
        float sA = 0.f, sB = 0.f;
        #pragma unroll
        for (int nt = 0; nt < 8; nt++){
            s[nt][0] = ex2(s[nt][0] - mnA);
            s[nt][1] = ex2(s[nt][1] - mnA);
            s[nt][2] = ex2(s[nt][2] - mnB);
            s[nt][3] = ex2(s[nt][3] - mnB);
            sA += s[nt][0] + s[nt][1];
            sB += s[nt][2] + s[nt][3];
        }
        sA += __shfl_xor_sync(0xffffffffu, sA, 1);
        sA += __shfl_xor_sync(0xffffffffu, sA, 2);
        sB += __shfl_xor_sync(0xffffffffu, sB, 1);
        sB += __shfl_xor_sync(0xffffffffu, sB, 2);
        l2[0] = l2[0]*aA + sA;  m2[0] = mnA;
        l2[1] = l2[1]*aB + sB;  m2[1] = mnB;
        #pragma unroll
        for (int nt = 0; nt < 8; nt++){
            o[nt][0] *= aA; o[nt][1] *= aA;
            o[nt][2] *= aB; o[nt][3] *= aB;
        }

        // --- O += P V (split 3-MMA) ---
        #pragma unroll
        for (int kc = 0; kc < 4; kc++){
            const float* pa = s[2*kc];
            const float* pb = s[2*kc + 1];
            uint32_t Ahi[4], Alo[4];
            split2(pa[0], pa[1], Ahi[0], Alo[0]);
            split2(pa[2], pa[3], Ahi[1], Alo[1]);
            split2(pb[0], pb[1], Ahi[2], Alo[2]);
            split2(pb[2], pb[3], Ahi[3], Alo[3]);

            uint32_t base = kc*16*KROW + rowad;
            #pragma unroll
            for (int dn2 = 0; dn2 < 4; dn2++){
                uint32_t bh0, bh1, bh2, bh3, bl0, bl1, bl2, bl3;
                LDSM4T(bh0, bh1, bh2, bh3, vhB + base + dn2*32);
                LDSM4T(bl0, bl1, bl2, bl3, vlB + base + dn2*32);
                MMA_BF16(o[dn2*2],     Ahi, bh0, bh1);
                MMA_BF16(o[dn2*2 + 1], Ahi, bh2, bh3);
                MMA_BF16(o[dn2*2],     Ahi, bl0, bl1);
                MMA_BF16(o[dn2*2 + 1], Ahi, bl2, bl3);
                MMA_BF16(o[dn2*2],     Alo, bh0, bh1);
                MMA_BF16(o[dn2*2 + 1], Alo, bh2, bh3);
            }
        }
    }

    // --- normalize + write split-bf16 ao [b, n, h*64+dh] ---
    float iA = 1.f / l2[0], iB = 1.f / l2[1];
    size_t rA = (size_t)b*NN + q0 + warp*16 + g;
    #pragma unroll
    for (int nt = 0; nt < 8; nt++){
        int col = h*64 + nt*8 + 2*t;
        uint32_t hi, lo;
        split2(o[nt][0]*iA, o[nt][1]*iA, hi, lo);
        *(uint32_t*)&g_aohi[rA*DD + col] = hi;
        *(uint32_t*)&g_aolo[rA*DD + col] = lo;
        split2(o[nt][2]*iB, o[nt][3]*iB, hi, lo);
        *(uint32_t*)&g_aohi[(rA + 8)*DD + col] = hi;
        *(uint32_t*)&g_aolo[(rA + 8)*DD + col] = lo;
    }
}

// ---------------------------------------------------------------------------
extern "C" void kernel_launch(void* const* d_in, const int* in_sizes, int n_in,
                              void* d_out, int out_size)
{
    const float* x       = (const float*)d_in[0];
    const float* context = (const float*)d_in[1];
    const float* Wq      = (const float*)d_in[2];
    const float* bq      = (const float*)d_in[3];
    const float* Wkv     = (const float*)d_in[4];
    const float* bkv     = (const float*)d_in[5];
    const float* Wo      = (const float*)d_in[6];
    const float* bo      = (const float*)d_in[7];
    float* out = (float*)d_out;

    cudaFuncSetAttribute(gemm_qkv,  cudaFuncAttributeMaxDynamicSharedMemorySize, GEMM_SMEM);
    cudaFuncSetAttribute(gemm_o,    cudaFuncAttributeMaxDynamicSharedMemorySize, GEMM_SMEM);
    cudaFuncSetAttribute(flash_mma, cudaFuncAttributeMaxDynamicSharedMemorySize, FA_SMEM);

    prep_all<<<NSPLIT_BLK + NTRANS_BLK, 256>>>(
        (const float4*)x, (const float4*)context, Wq, Wkv, Wo);

    gemm_qkv<<<1024, 256, GEMM_SMEM>>>(bq, bkv);
    flash_mma<<<dim3(NN/128, HH, BB), 256, FA_SMEM>>>();
    gemm_o<<<dim3(DD/128, (BB*NN)/128), 256, GEMM_SMEM>>>(bo, out);
}

// round 13
// speedup vs baseline: 1.0691x; 1.0691x over previous
#include <cuda_runtime.h>
#include <cuda_bf16.h>
#include <math.h>
#include <stdint.h>

// Problem constants
#define BB  2
#define NN  2048
#define MM  1024
#define LL  3072   // NN + MM
#define DD  1024
#define HH  16
#define DHH 64

#define SCALE_Q 0.18033688011112042f   // 0.125 * log2(e): softmax in exp2 domain

// ---------------------------------------------------------------------------
// Scratch (allocation-free rule: __device__ globals)
// K kept as bf16-hi ONLY (q·klo residual measured at ~6e-4 final rel err).
// ---------------------------------------------------------------------------
__device__ __align__(16) __nv_bfloat16 g_qhi[BB*HH*NN*DHH], g_qlo[BB*HH*NN*DHH];
__device__ __align__(16) __nv_bfloat16 g_khi[BB*HH*LL*DHH];
__device__ __align__(16) __nv_bfloat16 g_vhi[BB*HH*LL*DHH], g_vlo[BB*HH*LL*DHH];

__device__ __align__(16) __nv_bfloat16 g_xhi [BB*NN*DD], g_xlo [BB*NN*DD];
__device__ __align__(16) __nv_bfloat16 g_chi [BB*MM*DD], g_clo [BB*MM*DD];
__device__ __align__(16) __nv_bfloat16 g_wqt_hi [DD*DD],   g_wqt_lo [DD*DD];   // [n][k]
__device__ __align__(16) __nv_bfloat16 g_wkvt_hi[2*DD*DD], g_wkvt_lo[2*DD*DD]; // [n][k]
__device__ __align__(16) __nv_bfloat16 g_wot_hi [DD*DD],   g_wot_lo [DD*DD];   // [n][k]
__device__ __align__(16) __nv_bfloat16 g_aohi[BB*NN*DD], g_aolo[BB*NN*DD];

// ---------------------------------------------------------------------------
// Helpers
// ---------------------------------------------------------------------------
__device__ __forceinline__ uint32_t s2u(const void* p){
    uint32_t a;
    asm("{ .reg .u64 t; cvta.to.shared.u64 t, %1; cvt.u32.u64 %0, t; }" : "=r"(a) : "l"(p));
    return a;
}
__device__ __forceinline__ uint32_t bpack(__nv_bfloat16 a, __nv_bfloat16 b){
    return (uint32_t)__bfloat16_as_ushort(a) | ((uint32_t)__bfloat16_as_ushort(b) << 16);
}
__device__ __forceinline__ void cp16(uint32_t s, const void* g){
    asm volatile("cp.async.cg.shared.global [%0], [%1], 16;" :: "r"(s), "l"(g));
}
#define CP_COMMIT() asm volatile("cp.async.commit_group;")

__device__ __forceinline__ float ex2(float x){
    float y; asm("ex2.approx.f32 %0, %1;" : "=f"(y) : "f"(x)); return y;
}

#define MMA_BF16(C, A, b0, b1) \
    asm volatile("mma.sync.aligned.m16n8k16.row.col.f32.bf16.bf16.f32 " \
        "{%0,%1,%2,%3}, {%4,%5,%6,%7}, {%8,%9}, {%0,%1,%2,%3};" \
        : "+f"((C)[0]), "+f"((C)[1]), "+f"((C)[2]), "+f"((C)[3]) \
        : "r"((A)[0]), "r"((A)[1]), "r"((A)[2]), "r"((A)[3]), "r"(b0), "r"(b1))

#define LDSM4(r, addr) \
    asm volatile("ldmatrix.sync.aligned.m8n8.x4.shared.b16 {%0,%1,%2,%3}, [%4];" \
        : "=r"((r)[0]), "=r"((r)[1]), "=r"((r)[2]), "=r"((r)[3]) : "r"(addr))

#define LDSM4T(r0,r1,r2,r3,addr) \
    asm volatile("ldmatrix.sync.aligned.m8n8.x4.trans.shared.b16 {%0,%1,%2,%3}, [%4];" \
        : "=r"(r0), "=r"(r1), "=r"(r2), "=r"(r3) : "r"(addr))

__device__ __forceinline__ void split2(float x, float y, uint32_t& hi, uint32_t& lo){
    __nv_bfloat16 h0 = __float2bfloat16_rn(x), h1 = __float2bfloat16_rn(y);
    hi = bpack(h0, h1);
    lo = bpack(__float2bfloat16_rn(x - __bfloat162float(h0)),
               __float2bfloat16_rn(y - __bfloat162float(h1)));
}

// ---------------------------------------------------------------------------
// Prep: ONE kernel — splits x/context AND transposes+splits all weights.
// ---------------------------------------------------------------------------
#define NX4 (BB*NN*DD/4)
#define NC4 (BB*MM*DD/4)
#define NSPLIT_BLK ((NX4 + NC4) / 256)        // 6144
#define NTRANS_BLK (128 * 32)                 // 4096

__global__ __launch_bounds__(256) void prep_all(
    const float4* __restrict__ x, const float4* __restrict__ ctx,
    const float* __restrict__ Wq, const float* __restrict__ Wkv,
    const float* __restrict__ Wo)
{
    int bid = blockIdx.x;
    if (bid < NSPLIT_BLK){
        int i = bid * 256 + threadIdx.x;
        const float4* src;  uint2 *hi, *lo;  int j;
        if (i < NX4){ src = x;   hi = (uint2*)g_xhi; lo = (uint2*)g_xlo; j = i; }
        else        { src = ctx; hi = (uint2*)g_chi; lo = (uint2*)g_clo; j = i - NX4; }
        float4 v = src[j];
        uint32_t h0, l0, h1, l1;
        split2(v.x, v.y, h0, l0);
        split2(v.z, v.w, h1, l1);
        hi[j] = make_uint2(h0, h1);
        lo[j] = make_uint2(l0, l1);
        return;
    }
    int id = bid - NSPLIT_BLK;
    int cx = id & 127, ky = id >> 7;
    const float* W; __nv_bfloat16 *th, *tl; int N, n0;
    if (cx < 32){       W = Wq;  N = 1024; n0 = cx*32;      th = g_wqt_hi;  tl = g_wqt_lo;  }
    else if (cx < 96){  W = Wkv; N = 2048; n0 = (cx-32)*32; th = g_wkvt_hi; tl = g_wkvt_lo; }
    else{               W = Wo;  N = 1024; n0 = (cx-96)*32; th = g_wot_hi;  tl = g_wot_lo;  }

    __shared__ float t[32][33];
    int k0 = ky * 32;
    int tx = threadIdx.x & 31, ty = threadIdx.x >> 5;
    #pragma unroll
    for (int r = 0; r < 4; r++)
        t[ty + r*8][tx] = W[(size_t)(k0 + ty + r*8) * N + n0 + tx];
    __syncthreads();
    #pragma unroll
    for (int r = 0; r < 4; r++){
        int n = ty + r*8;
        float v = t[tx][n];
        __nv_bfloat16 h = __float2bfloat16_rn(v);
        __nv_bfloat16 l = __float2bfloat16_rn(v - __bfloat162float(h));
        size_t o = (size_t)(n0 + n) * 1024 + k0 + tx;
        th[o] = h; tl[o] = l;
    }
}

// ---------------------------------------------------------------------------
// Shared GEMM machinery: 128x128 CTA tile, BK=32, double-buffered cp.async,
// one __syncthreads per K-iter, product-major MMA ordering. (round-7 exact,
// proven 82us/wave; frozen)
// ---------------------------------------------------------------------------
#define PITCH 80
#define MATB  (128*PITCH)
#define STAGEB (4*MATB)
#define GEMM_SMEM (2*STAGEB)

// Fused Q + KV projection: 1024 CTAs. cid<256 -> Q tile; else KV tile.
__global__ __launch_bounds__(256, 2) void gemm_qkv(const float* __restrict__ bq,
                                                   const float* __restrict__ bkv)
{
    extern __shared__ char sm[];
    const int tid  = threadIdx.x;
    const int lane = tid & 31;
    const int warp = tid >> 5;
    const int wM = warp & 3, wN = warp >> 2;
    const int g  = lane >> 2, t = lane & 3;

    const int cid = blockIdx.x;
    const bool isQ = (cid < 256);
    int rowBase, colBase;
    const __nv_bfloat16 *Bh, *Bl;
    const float* bias;
    if (isQ){
        rowBase = (cid >> 3) * 128;  colBase = (cid & 7) * 128;
        Bh = g_wqt_hi;  Bl = g_wqt_lo;  bias = bq;
    } else {
        int c2 = cid - 256;
        rowBase = (c2 >> 4) * 128;   colBase = (c2 & 15) * 128;
        Bh = g_wkvt_hi; Bl = g_wkvt_lo; bias = bkv;
    }

    int      lr[2];  uint32_t lcb[2];
    const char *pAh[2], *pAl[2], *pBh[2], *pBl[2];
    #pragma unroll
    for (int j = 0; j < 2; j++){
        int idx = tid + j * 256;
        lr[j]  = idx >> 2;
        lcb[j] = (idx & 3) * 16;
        int row = rowBase + lr[j];
        const __nv_bfloat16 *ah, *al; size_t ro;
        if (isQ){
            ah = g_xhi;  al = g_xlo;  ro = (size_t)row * DD;
        } else {
            int b = row / LL, jj = row % LL;
            if (jj < NN){ ah = g_xhi; al = g_xlo; ro = (size_t)(b*NN + jj) * DD; }
            else        { ah = g_chi; al = g_clo; ro = (size_t)(b*MM + jj - NN) * DD; }
        }
        pAh[j] = (const char*)(ah + ro);
        pAl[j] = (const char*)(al + ro);
        size_t bo = (size_t)(colBase + lr[j]) * DD;
        pBh[j] = (const char*)(Bh + bo);
        pBl[j] = (const char*)(Bl + bo);
    }

    const uint32_t smBase = s2u(sm);
    auto load_stage = [&](int k0, int stage){
        uint32_t sb = smBase + stage * STAGEB;
        #pragma unroll
        for (int j = 0; j < 2; j++){
            uint32_t so = lr[j] * PITCH + lcb[j];
            size_t   go = (size_t)k0 * 2 + lcb[j];
            cp16(sb + so,          pAh[j] + go);
            cp16(sb + MATB + so,   pAl[j] + go);
            cp16(sb + 2*MATB + so, pBh[j] + go);
            cp16(sb + 3*MATB + so, pBl[j] + go);
        }
        CP_COMMIT();
    };

    float c[2][8][4];
    #pragma unroll
    for (int mt = 0; mt < 2; mt++)
        #pragma unroll
        for (int nt = 0; nt < 8; nt++)
            #pragma unroll
            for (int i = 0; i < 4; i++) c[mt][nt][i] = 0.f;

    const uint32_t aRow = (lane & 7) + ((lane >> 3) & 1) * 8;
    const uint32_t aK   = ((lane >> 4) & 1) * 16;
    const uint32_t bRow = (lane & 7) + ((lane >> 4) & 1) * 8;
    const uint32_t bK   = ((lane >> 3) & 1) * 16;

    load_stage(0, 0);

    for (int it = 0; it < 32; ++it){
        asm volatile("cp.async.wait_group 0;" ::: "memory");
        __syncthreads();
        if (it + 1 < 32) load_stage((it + 1) * 32, (it + 1) & 1);

        const uint32_t sbu = smBase + (it & 1) * STAGEB;
        #pragma unroll
        for (int ks = 0; ks < 2; ks++){
            uint32_t a0[2][4], a1[2][4];
            #pragma unroll
            for (int mt = 0; mt < 2; mt++){
                LDSM4(a0[mt], sbu + (wM*32 + mt*16 + aRow)*PITCH + ks*32 + aK);
                LDSM4(a1[mt], sbu + MATB + (wM*32 + mt*16 + aRow)*PITCH + ks*32 + aK);
            }
            #pragma unroll
            for (int ntp = 0; ntp < 4; ntp++){
                uint32_t bh[4], bl[4];
                uint32_t bro = (wN*64 + ntp*16 + bRow)*PITCH + ks*32 + bK;
                LDSM4(bh, sbu + 2*MATB + bro);
                LDSM4(bl, sbu + 3*MATB + bro);
                #pragma unroll
                for (int hf = 0; hf < 2; hf++)
                    #pragma unroll
                    for (int mt = 0; mt < 2; mt++)
                        MMA_BF16(c[mt][ntp*2+hf], a0[mt], bh[hf*2], bh[hf*2+1]);
                #pragma unroll
                for (int hf = 0; hf < 2; hf++)
                    #pragma unroll
                    for (int mt = 0; mt < 2; mt++)
                        MMA_BF16(c[mt][ntp*2+hf], a0[mt], bl[hf*2], bl[hf*2+1]);
                #pragma unroll
                for (int hf = 0; hf < 2; hf++)
                    #pragma unroll
                    for (int mt = 0; mt < 2; mt++)
                        MMA_BF16(c[mt][ntp*2+hf], a1[mt], bh[hf*2], bh[hf*2+1]);
            }
        }
    }

    // --- epilogue ---
    #pragma unroll
    for (int mt = 0; mt < 2; mt++){
        int row0 = rowBase + wM*32 + mt*16 + g;
        #pragma unroll
        for (int nt = 0; nt < 8; nt++){
            int col = colBase + wN*64 + nt*8 + t*2;
            float2 bz = *(const float2*)(bias + col);
            #pragma unroll
            for (int hrow = 0; hrow < 2; hrow++){
                int row = row0 + hrow*8;
                float vx = c[mt][nt][hrow*2]   + bz.x;
                float vy = c[mt][nt][hrow*2+1] + bz.y;
                if (isQ){
                    int b = row / NN, qi = row % NN;
                    int hh = col >> 6, d2 = col & 63;
                    uint32_t hi, lo;
                    split2(vx * SCALE_Q, vy * SCALE_Q, hi, lo);
                    size_t o = ((size_t)(b*HH + hh) * NN + qi) * DHH + d2;
                    *(uint32_t*)&g_qhi[o] = hi;
                    *(uint32_t*)&g_qlo[o] = lo;
                } else {
                    int b = row / LL, jj = row % LL;
                    if (col < DD){
                        int hh = col >> 6, d2 = col & 63;
                        size_t o = ((size_t)(b*HH + hh) * LL + jj) * DHH + d2;
                        *(uint32_t*)&g_khi[o] =
                            bpack(__float2bfloat16_rn(vx), __float2bfloat16_rn(vy));
                    } else {
                        int c2 = col - DD;
                        int hh = c2 >> 6, d2 = c2 & 63;
                        uint32_t hi, lo;
                        split2(vx, vy, hi, lo);
                        size_t o = ((size_t)(b*HH + hh) * LL + jj) * DHH + d2;
                        *(uint32_t*)&g_vhi[o] = hi;
                        *(uint32_t*)&g_vlo[o] = lo;
                    }
                }
            }
        }
    }
}

// O-projection: out = ao @ Wo + bo  (round-7 exact)
__global__ __launch_bounds__(256, 2) void gemm_o(const float* __restrict__ bias,
                                                 float* __restrict__ out)
{
    extern __shared__ char sm[];
    const int tid  = threadIdx.x;
    const int lane = tid & 31;
    const int warp = tid >> 5;
    const int wM = warp & 3, wN = warp >> 2;
    const int g  = lane >> 2, t = lane & 3;

    const int rowBase = blockIdx.y * 128;
    const int colBase = blockIdx.x * 128;

    int      lr[2];  uint32_t lcb[2];
    const char *pAh[2], *pAl[2], *pBh[2], *pBl[2];
    #pragma unroll
    for (int j = 0; j < 2; j++){
        int idx = tid + j * 256;
        lr[j]  = idx >> 2;
        lcb[j] = (idx & 3) * 16;
        size_t ro = (size_t)(rowBase + lr[j]) * DD;
        pAh[j] = (const char*)(g_aohi + ro);
        pAl[j] = (const char*)(g_aolo + ro);
        size_t bo = (size_t)(colBase + lr[j]) * DD;
        pBh[j] = (const char*)(g_wot_hi + bo);
        pBl[j] = (const char*)(g_wot_lo + bo);
    }

    const uint32_t smBase = s2u(sm);
    auto load_stage = [&](int k0, int stage){
        uint32_t sb = smBase + stage * STAGEB;
        #pragma unroll
        for (int j = 0; j < 2; j++){
            uint32_t so = lr[j] * PITCH + lcb[j];
            size_t   go = (size_t)k0 * 2 + lcb[j];
            cp16(sb + so,          pAh[j] + go);
            cp16(sb + MATB + so,   pAl[j] + go);
            cp16(sb + 2*MATB + so, pBh[j] + go);
            cp16(sb + 3*MATB + so, pBl[j] + go);
        }
        CP_COMMIT();
    };

    float c[2][8][4];
    #pragma unroll
    for (int mt = 0; mt < 2; mt++)
        #pragma unroll
        for (int nt = 0; nt < 8; nt++)
            #pragma unroll
            for (int i = 0; i < 4; i++) c[mt][nt][i] = 0.f;

    const uint32_t aRow = (lane & 7) + ((lane >> 3) & 1) * 8;
    const uint32_t aK   = ((lane >> 4) & 1) * 16;
    const uint32_t bRow = (lane & 7) + ((lane >> 4) & 1) * 8;
    const uint32_t bK   = ((lane >> 3) & 1) * 16;

    load_stage(0, 0);

    for (int it = 0; it < 32; ++it){
        asm volatile("cp.async.wait_group 0;" ::: "memory");
        __syncthreads();
        if (it + 1 < 32) load_stage((it + 1) * 32, (it + 1) & 1);

        const uint32_t sbu = smBase + (it & 1) * STAGEB;
        #pragma unroll
        for (int ks = 0; ks < 2; ks++){
            uint32_t a0[2][4], a1[2][4];
            #pragma unroll
            for (int mt = 0; mt < 2; mt++){
                LDSM4(a0[mt], sbu + (wM*32 + mt*16 + aRow)*PITCH + ks*32 + aK);
                LDSM4(a1[mt], sbu + MATB + (wM*32 + mt*16 + aRow)*PITCH + ks*32 + aK);
            }
            #pragma unroll
            for (int ntp = 0; ntp < 4; ntp++){
                uint32_t bh[4], bl[4];
                uint32_t bro = (wN*64 + ntp*16 + bRow)*PITCH + ks*32 + bK;
                LDSM4(bh, sbu + 2*MATB + bro);
                LDSM4(bl, sbu + 3*MATB + bro);
                #pragma unroll
                for (int hf = 0; hf < 2; hf++)
                    #pragma unroll
                    for (int mt = 0; mt < 2; mt++)
                        MMA_BF16(c[mt][ntp*2+hf], a0[mt], bh[hf*2], bh[hf*2+1]);
                #pragma unroll
                for (int hf = 0; hf < 2; hf++)
                    #pragma unroll
                    for (int mt = 0; mt < 2; mt++)
                        MMA_BF16(c[mt][ntp*2+hf], a0[mt], bl[hf*2], bl[hf*2+1]);
                #pragma unroll
                for (int hf = 0; hf < 2; hf++)
                    #pragma unroll
                    for (int mt = 0; mt < 2; mt++)
                        MMA_BF16(c[mt][ntp*2+hf], a1[mt], bh[hf*2], bh[hf*2+1]);
            }
        }
    }

    #pragma unroll
    for (int mt = 0; mt < 2; mt++){
        int row0 = rowBase + wM*32 + mt*16 + g;
        #pragma unroll
        for (int nt = 0; nt < 8; nt++){
            int col = colBase + wN*64 + nt*8 + t*2;
            float2 bz = *(const float2*)(bias + col);
            #pragma unroll
            for (int hrow = 0; hrow < 2; hrow++){
                int row = row0 + hrow*8;
                *(float2*)&out[(size_t)row * DD + col] =
                    make_float2(c[mt][nt][hrow*2] + bz.x, c[mt][nt][hrow*2+1] + bz.y);
            }
        }
    }
}

// ---------------------------------------------------------------------------
// HMMA flash attention (round-10 structure): 128 q/CTA, 8 warps x 16 rows,
// 64-key tiles, K bf16-hi only, PV 3-term split, ex2 softmax, heavy-first.
// NEW: THREE-stage KV ring, prefetch depth 2, steady-state wait_group 1.
// ---------------------------------------------------------------------------
#define KROW    144
#define KVMAT   (64*KROW)
#define KVSTAGE (3*KVMAT)            // Khi, Vhi, Vlo = 27648 B per stage
#define FA_NST  3
#define FA_SMEM (FA_NST*KVSTAGE)     // 82944 B (2 CTAs/SM: 165888 <= 227KB)

__global__ __launch_bounds__(256, 2) void flash_mma()
{
    extern __shared__ char fsm[];
    const int tid = threadIdx.x, lane = tid & 31, warp = tid >> 5;
    const int g = lane >> 2, t = lane & 3;
    const int q0 = (int)(gridDim.x - 1 - blockIdx.x) * 128;   // heavy-first
    const int h  = blockIdx.y;
    const int b  = blockIdx.z;

    const __nv_bfloat16* qh = g_qhi + ((size_t)(b*HH + h) * NN + q0 + warp*16) * DHH;
    const __nv_bfloat16* ql = g_qlo + ((size_t)(b*HH + h) * NN + q0 + warp*16) * DHH;
    uint32_t qa[2][4][4];
    #pragma unroll
    for (int kc = 0; kc < 4; kc++){
        int e0 = g*DHH + kc*16 + 2*t;
        qa[0][kc][0] = *(const uint32_t*)(qh + e0);
        qa[0][kc][1] = *(const uint32_t*)(qh + e0 + 8*DHH);
        qa[0][kc][2] = *(const uint32_t*)(qh + e0 + 8);
        qa[0][kc][3] = *(const uint32_t*)(qh + e0 + 8*DHH + 8);
        qa[1][kc][0] = *(const uint32_t*)(ql + e0);
        qa[1][kc][1] = *(const uint32_t*)(ql + e0 + 8*DHH);
        qa[1][kc][2] = *(const uint32_t*)(ql + e0 + 8);
        qa[1][kc][3] = *(const uint32_t*)(ql + e0 + 8*DHH + 8);
    }

    float o[8][4];
    #pragma unroll
    for (int nt = 0; nt < 8; nt++)
        #pragma unroll
        for (int i = 0; i < 4; i++) o[nt][i] = 0.f;
    float m2[2] = {-1e30f, -1e30f}, l2[2] = {0.f, 0.f};

    const size_t kvbase = (size_t)(b*HH + h) * LL;
    const int nSelf = q0/64 + 2;
    const int nBlk  = nSelf + MM/64;
    auto jof = [&](int blk){ return blk < nSelf ? blk*64 : NN + (blk - nSelf)*64; };

    const uint32_t fsb = s2u(fsm);
    auto load_kv = [&](int blk){
        uint32_t sb = fsb + (blk % FA_NST) * KVSTAGE;
        size_t go = (kvbase + jof(blk)) * DHH;
        #pragma unroll
        for (int i = 0; i < 2; i++){
            int idx = tid + i*256;          // 0..511 = 64 rows x 8 chunks
            int r = idx >> 3, cb = (idx & 7) * 16;
            uint32_t so = r*KROW + cb;
            size_t ge = go + (size_t)r*DHH + (cb >> 1);
            cp16(sb + so,           g_khi + ge);
            cp16(sb + KVMAT + so,   g_vhi + ge);
            cp16(sb + 2*KVMAT + so, g_vlo + ge);
        }
        CP_COMMIT();
    };

    const uint32_t kRowL = (lane & 7) + ((lane >> 4) & 1) * 8;
    const uint32_t kKL   = ((lane >> 3) & 1) * 16;
    const uint32_t rowad = (lane & 7)*KROW + ((lane >> 4) & 1)*16 +
                           (((lane >> 3) & 1) ? 8*KROW : 0);

    load_kv(0);
    if (nBlk > 1) load_kv(1);

    for (int blk = 0; blk < nBlk; ++blk){
        const int j0 = jof(blk);
        // steady state: allow the depth-2 prefetch to stay in flight
        if (blk + 1 < nBlk) { asm volatile("cp.async.wait_group 1;" ::: "memory"); }
        else                { asm volatile("cp.async.wait_group 0;" ::: "memory"); }
        __syncthreads();
        if (blk + 2 < nBlk) load_kv(blk + 2);

        const uint32_t stU = fsb + (blk % FA_NST) * KVSTAGE;
        const uint32_t KhU = stU;
        const uint32_t vhB = stU + KVMAT;
        const uint32_t vlB = stU + 2*KVMAT;

        // --- S = (qhi + qlo) · khi ---
        float s[8][4];
        #pragma unroll
        for (int nt = 0; nt < 8; nt++)
            s[nt][0] = s[nt][1] = s[nt][2] = s[nt][3] = 0.f;
        #pragma unroll
        for (int kc = 0; kc < 4; kc++){
            #pragma unroll
            for (int ntp = 0; ntp < 4; ntp++){
                uint32_t bh[4];
                LDSM4(bh, KhU + (ntp*16 + kRowL)*KROW + kc*32 + kKL);
                MMA_BF16(s[ntp*2],   qa[0][kc], bh[0], bh[1]);
                MMA_BF16(s[ntp*2+1], qa[0][kc], bh[2], bh[3]);
                MMA_BF16(s[ntp*2],   qa[1][kc], bh[0], bh[1]);
                MMA_BF16(s[ntp*2+1], qa[1][kc], bh[2], bh[3]);
            }
        }

        // --- causal mask (last two self tiles only) ---
        if (blk >= nSelf - 2 && blk < nSelf){
            int rA = q0 + warp*16 + g, rB = rA + 8;
            #pragma unroll
            for (int nt = 0; nt < 8; nt++){
                int k0 = j0 + nt*8 + 2*t;
                if (k0     > rA) s[nt][0] = -1e30f;
                if (k0 + 1 > rA) s[nt][1] = -1e30f;
                if (k0     > rB) s[nt][2] = -1e30f;
                if (k0 + 1 > rB) s[nt][3] = -1e30f;
            }
        }

        // --- online softmax (exp2 domain) ---
        float mxA = -1e30f, mxB = -1e30f;
        #pragma unroll
        for (int nt = 0; nt < 8; nt++){
            mxA = fmaxf(mxA, fmaxf(s[nt][0], s[nt][1]));
            mxB = fmaxf(mxB, fmaxf(s[nt][2], s[nt][3]));
        }
        mxA = fmaxf(mxA, __shfl_xor_sync(0xffffffffu, mxA, 1));
        mxA = fmaxf(mxA, __shfl_xor_sync(0xffffffffu, mxA, 2));
        mxB = fmaxf(mxB, __shfl_xor_sync(0xffffffffu, mxB, 1));
        mxB = fmaxf(mxB, __shfl_xor_sync(0xffffffffu, mxB, 2));

        float mnA = fmaxf(m2[0], mxA), mnB = fmaxf(m2[1], mxB);
        float aA = ex2(m2[0] - mnA), aB = ex2(m2[1] - mnB);
        float sA = 0.f, sB = 0.f;
        #pragma unroll
        for (int nt = 0; nt < 8; nt++){
            s[nt][0] = ex2(s[nt][0] - mnA);
            s[nt][1] = ex2(s[nt][1] - mnA);
            s[nt][2] = ex2(s[nt][2] - mnB);
            s[nt][3] = ex2(s[nt][3] - mnB);
            sA += s[nt][0] + s[nt][1];
            sB += s[nt][2] + s[nt][3];
        }
        sA += __shfl_xor_sync(0xffffffffu, sA, 1);
        sA += __shfl_xor_sync(0xffffffffu, sA, 2);
        sB += __shfl_xor_sync(0xffffffffu, sB, 1);
        sB += __shfl_xor_sync(0xffffffffu, sB, 2);
        l2[0] = l2[0]*aA + sA;  m2[0] = mnA;
        l2[1] = l2[1]*aB + sB;  m2[1] = mnB;
        #pragma unroll
        for (int nt = 0; nt < 8; nt++){
            o[nt][0] *= aA; o[nt][1] *= aA;
            o[nt][2] *= aB; o[nt][3] *= aB;
        }

        // --- O += P V (split 3-MMA) ---
        #pragma unroll
        for (int kc = 0; kc < 4; kc++){
            const float* pa = s[2*kc];
            const float* pb = s[2*kc + 1];
            uint32_t Ahi[4], Alo[4];
            split2(pa[0], pa[1], Ahi[0], Alo[0]);
            split2(pa[2], pa[3], Ahi[1], Alo[1]);
            split2(pb[0], pb[1], Ahi[2], Alo[2]);
            split2(pb[2], pb[3], Ahi[3], Alo[3]);

            uint32_t base = kc*16*KROW + rowad;
            #pragma unroll
            for (int dn2 = 0; dn2 < 4; dn2++){
                uint32_t bh0, bh1, bh2, bh3, bl0, bl1, bl2, bl3;
                LDSM4T(bh0, bh1, bh2, bh3, vhB + base + dn2*32);
                LDSM4T(bl0, bl1, bl2, bl3, vlB + base + dn2*32);
                MMA_BF16(o[dn2*2],     Ahi, bh0, bh1);
                MMA_BF16(o[dn2*2 + 1], Ahi, bh2, bh3);
                MMA_BF16(o[dn2*2],     Ahi, bl0, bl1);
                MMA_BF16(o[dn2*2 + 1], Ahi, bl2, bl3);
                MMA_BF16(o[dn2*2],     Alo, bh0, bh1);
                MMA_BF16(o[dn2*2 + 1], Alo, bh2, bh3);
            }
        }
    }

    // --- normalize + write split-bf16 ao [b, n, h*64+dh] ---
    float iA = 1.f / l2[0], iB = 1.f / l2[1];
    size_t rA = (size_t)b*NN + q0 + warp*16 + g;
    #pragma unroll
    for (int nt = 0; nt < 8; nt++){
        int col = h*64 + nt*8 + 2*t;
        uint32_t hi, lo;
        split2(o[nt][0]*iA, o[nt][1]*iA, hi, lo);
        *(uint32_t*)&g_aohi[rA*DD + col] = hi;
        *(uint32_t*)&g_aolo[rA*DD + col] = lo;
        split2(o[nt][2]*iB, o[nt][3]*iB, hi, lo);
        *(uint32_t*)&g_aohi[(rA + 8)*DD + col] = hi;
        *(uint32_t*)&g_aolo[(rA + 8)*DD + col] = lo;
    }
}

// ---------------------------------------------------------------------------
extern "C" void kernel_launch(void* const* d_in, const int* in_sizes, int n_in,
                              void* d_out, int out_size)
{
    const float* x       = (const float*)d_in[0];
    const float* context = (const float*)d_in[1];
    const float* Wq      = (const float*)d_in[2];
    const float* bq      = (const float*)d_in[3];
    const float* Wkv     = (const float*)d_in[4];
    const float* bkv     = (const float*)d_in[5];
    const float* Wo      = (const float*)d_in[6];
    const float* bo      = (const float*)d_in[7];
    float* out = (float*)d_out;

    cudaFuncSetAttribute(gemm_qkv,  cudaFuncAttributeMaxDynamicSharedMemorySize, GEMM_SMEM);
    cudaFuncSetAttribute(gemm_o,    cudaFuncAttributeMaxDynamicSharedMemorySize, GEMM_SMEM);
    cudaFuncSetAttribute(flash_mma, cudaFuncAttributeMaxDynamicSharedMemorySize, FA_SMEM);

    prep_all<<<NSPLIT_BLK + NTRANS_BLK, 256>>>(
        (const float4*)x, (const float4*)context, Wq, Wkv, Wo);

    gemm_qkv<<<1024, 256, GEMM_SMEM>>>(bq, bkv);
    flash_mma<<<dim3(NN/128, HH, BB), 256, FA_SMEM>>>();
    gemm_o<<<dim3(DD/128, (BB*NN)/128), 256, GEMM_SMEM>>>(bo, out);
}

// round 14
// speedup vs baseline: 1.1205x; 1.0481x over previous
#include <cuda_runtime.h>
#include <cuda_bf16.h>
#include <math.h>
#include <stdint.h>

// Problem constants
#define BB  2
#define NN  2048
#define MM  1024
#define LL  3072   // NN + MM
#define DD  1024
#define HH  16
#define DHH 64

#define SCALE_Q 0.18033688011112042f   // 0.125 * log2(e): softmax in exp2 domain

// ---------------------------------------------------------------------------
// Scratch (allocation-free rule: __device__ globals)
// K kept as bf16-hi ONLY (q·klo residual measured at ~6e-4 final rel err).
// ---------------------------------------------------------------------------
__device__ __align__(16) __nv_bfloat16 g_qhi[BB*HH*NN*DHH], g_qlo[BB*HH*NN*DHH];
__device__ __align__(16) __nv_bfloat16 g_khi[BB*HH*LL*DHH];
__device__ __align__(16) __nv_bfloat16 g_vhi[BB*HH*LL*DHH], g_vlo[BB*HH*LL*DHH];

__device__ __align__(16) __nv_bfloat16 g_xhi [BB*NN*DD], g_xlo [BB*NN*DD];
__device__ __align__(16) __nv_bfloat16 g_chi [BB*MM*DD], g_clo [BB*MM*DD];
__device__ __align__(16) __nv_bfloat16 g_wqt_hi [DD*DD],   g_wqt_lo [DD*DD];   // [n][k]
__device__ __align__(16) __nv_bfloat16 g_wkvt_hi[2*DD*DD], g_wkvt_lo[2*DD*DD]; // [n][k]
__device__ __align__(16) __nv_bfloat16 g_wot_hi [DD*DD],   g_wot_lo [DD*DD];   // [n][k]
__device__ __align__(16) __nv_bfloat16 g_aohi[BB*NN*DD], g_aolo[BB*NN*DD];

// ---------------------------------------------------------------------------
// Helpers
// ---------------------------------------------------------------------------
__device__ __forceinline__ uint32_t s2u(const void* p){
    uint32_t a;
    asm("{ .reg .u64 t; cvta.to.shared.u64 t, %1; cvt.u32.u64 %0, t; }" : "=r"(a) : "l"(p));
    return a;
}
__device__ __forceinline__ uint32_t bpack(__nv_bfloat16 a, __nv_bfloat16 b){
    return (uint32_t)__bfloat16_as_ushort(a) | ((uint32_t)__bfloat16_as_ushort(b) << 16);
}
__device__ __forceinline__ void cp16(uint32_t s, const void* g){
    asm volatile("cp.async.cg.shared.global [%0], [%1], 16;" :: "r"(s), "l"(g));
}
#define CP_COMMIT() asm volatile("cp.async.commit_group;")

__device__ __forceinline__ float ex2(float x){
    float y; asm("ex2.approx.f32 %0, %1;" : "=f"(y) : "f"(x)); return y;
}

#define MMA_BF16(C, A, b0, b1) \
    asm volatile("mma.sync.aligned.m16n8k16.row.col.f32.bf16.bf16.f32 " \
        "{%0,%1,%2,%3}, {%4,%5,%6,%7}, {%8,%9}, {%0,%1,%2,%3};" \
        : "+f"((C)[0]), "+f"((C)[1]), "+f"((C)[2]), "+f"((C)[3]) \
        : "r"((A)[0]), "r"((A)[1]), "r"((A)[2]), "r"((A)[3]), "r"(b0), "r"(b1))

#define LDSM4(r, addr) \
    asm volatile("ldmatrix.sync.aligned.m8n8.x4.shared.b16 {%0,%1,%2,%3}, [%4];" \
        : "=r"((r)[0]), "=r"((r)[1]), "=r"((r)[2]), "=r"((r)[3]) : "r"(addr))

#define LDSM4T(r0,r1,r2,r3,addr) \
    asm volatile("ldmatrix.sync.aligned.m8n8.x4.trans.shared.b16 {%0,%1,%2,%3}, [%4];" \
        : "=r"(r0), "=r"(r1), "=r"(r2), "=r"(r3) : "r"(addr))

__device__ __forceinline__ void split2(float x, float y, uint32_t& hi, uint32_t& lo){
    __nv_bfloat16 h0 = __float2bfloat16_rn(x), h1 = __float2bfloat16_rn(y);
    hi = bpack(h0, h1);
    lo = bpack(__float2bfloat16_rn(x - __bfloat162float(h0)),
               __float2bfloat16_rn(y - __bfloat162float(h1)));
}

// ---------------------------------------------------------------------------
// Prep: ONE kernel — splits x/context AND transposes+splits all weights.
// ---------------------------------------------------------------------------
#define NX4 (BB*NN*DD/4)
#define NC4 (BB*MM*DD/4)
#define NSPLIT_BLK ((NX4 + NC4) / 256)        // 6144
#define NTRANS_BLK (128 * 32)                 // 4096

__global__ __launch_bounds__(256) void prep_all(
    const float4* __restrict__ x, const float4* __restrict__ ctx,
    const float* __restrict__ Wq, const float* __restrict__ Wkv,
    const float* __restrict__ Wo)
{
    int bid = blockIdx.x;
    if (bid < NSPLIT_BLK){
        int i = bid * 256 + threadIdx.x;
        const float4* src;  uint2 *hi, *lo;  int j;
        if (i < NX4){ src = x;   hi = (uint2*)g_xhi; lo = (uint2*)g_xlo; j = i; }
        else        { src = ctx; hi = (uint2*)g_chi; lo = (uint2*)g_clo; j = i - NX4; }
        float4 v = src[j];
        uint32_t h0, l0, h1, l1;
        split2(v.x, v.y, h0, l0);
        split2(v.z, v.w, h1, l1);
        hi[j] = make_uint2(h0, h1);
        lo[j] = make_uint2(l0, l1);
        return;
    }
    int id = bid - NSPLIT_BLK;
    int cx = id & 127, ky = id >> 7;
    const float* W; __nv_bfloat16 *th, *tl; int N, n0;
    if (cx < 32){       W = Wq;  N = 1024; n0 = cx*32;      th = g_wqt_hi;  tl = g_wqt_lo;  }
    else if (cx < 96){  W = Wkv; N = 2048; n0 = (cx-32)*32; th = g_wkvt_hi; tl = g_wkvt_lo; }
    else{               W = Wo;  N = 1024; n0 = (cx-96)*32; th = g_wot_hi;  tl = g_wot_lo;  }

    __shared__ float t[32][33];
    int k0 = ky * 32;
    int tx = threadIdx.x & 31, ty = threadIdx.x >> 5;
    #pragma unroll
    for (int r = 0; r < 4; r++)
        t[ty + r*8][tx] = W[(size_t)(k0 + ty + r*8) * N + n0 + tx];
    __syncthreads();
    #pragma unroll
    for (int r = 0; r < 4; r++){
        int n = ty + r*8;
        float v = t[tx][n];
        __nv_bfloat16 h = __float2bfloat16_rn(v);
        __nv_bfloat16 l = __float2bfloat16_rn(v - __bfloat162float(h));
        size_t o = (size_t)(n0 + n) * 1024 + k0 + tx;
        th[o] = h; tl[o] = l;
    }
}

// ---------------------------------------------------------------------------
// Shared GEMM machinery: 128x128 CTA tile, BK=32, double-buffered cp.async,
// one __syncthreads per K-iter, product-major MMA ordering. (round-7 exact;
// proven local optimum, frozen)
// ---------------------------------------------------------------------------
#define PITCH 80
#define MATB  (128*PITCH)
#define STAGEB (4*MATB)
#define GEMM_SMEM (2*STAGEB)

// Fused Q + KV projection: 1024 CTAs. cid<256 -> Q tile; else KV tile.
__global__ __launch_bounds__(256, 2) void gemm_qkv(const float* __restrict__ bq,
                                                   const float* __restrict__ bkv)
{
    extern __shared__ char sm[];
    const int tid  = threadIdx.x;
    const int lane = tid & 31;
    const int warp = tid >> 5;
    const int wM = warp & 3, wN = warp >> 2;
    const int g  = lane >> 2, t = lane & 3;

    const int cid = blockIdx.x;
    const bool isQ = (cid < 256);
    int rowBase, colBase;
    const __nv_bfloat16 *Bh, *Bl;
    const float* bias;
    if (isQ){
        rowBase = (cid >> 3) * 128;  colBase = (cid & 7) * 128;
        Bh = g_wqt_hi;  Bl = g_wqt_lo;  bias = bq;
    } else {
        int c2 = cid - 256;
        rowBase = (c2 >> 4) * 128;   colBase = (c2 & 15) * 128;
        Bh = g_wkvt_hi; Bl = g_wkvt_lo; bias = bkv;
    }

    int      lr[2];  uint32_t lcb[2];
    const char *pAh[2], *pAl[2], *pBh[2], *pBl[2];
    #pragma unroll
    for (int j = 0; j < 2; j++){
        int idx = tid + j * 256;
        lr[j]  = idx >> 2;
        lcb[j] = (idx & 3) * 16;
        int row = rowBase + lr[j];
        const __nv_bfloat16 *ah, *al; size_t ro;
        if (isQ){
            ah = g_xhi;  al = g_xlo;  ro = (size_t)row * DD;
        } else {
            int b = row / LL, jj = row % LL;
            if (jj < NN){ ah = g_xhi; al = g_xlo; ro = (size_t)(b*NN + jj) * DD; }
            else        { ah = g_chi; al = g_clo; ro = (size_t)(b*MM + jj - NN) * DD; }
        }
        pAh[j] = (const char*)(ah + ro);
        pAl[j] = (const char*)(al + ro);
        size_t bo = (size_t)(colBase + lr[j]) * DD;
        pBh[j] = (const char*)(Bh + bo);
        pBl[j] = (const char*)(Bl + bo);
    }

    const uint32_t smBase = s2u(sm);
    auto load_stage = [&](int k0, int stage){
        uint32_t sb = smBase + stage * STAGEB;
        #pragma unroll
        for (int j = 0; j < 2; j++){
            uint32_t so = lr[j] * PITCH + lcb[j];
            size_t   go = (size_t)k0 * 2 + lcb[j];
            cp16(sb + so,          pAh[j] + go);
            cp16(sb + MATB + so,   pAl[j] + go);
            cp16(sb + 2*MATB + so, pBh[j] + go);
            cp16(sb + 3*MATB + so, pBl[j] + go);
        }
        CP_COMMIT();
    };

    float c[2][8][4];
    #pragma unroll
    for (int mt = 0; mt < 2; mt++)
        #pragma unroll
        for (int nt = 0; nt < 8; nt++)
            #pragma unroll
            for (int i = 0; i < 4; i++) c[mt][nt][i] = 0.f;

    const uint32_t aRow = (lane & 7) + ((lane >> 3) & 1) * 8;
    const uint32_t aK   = ((lane >> 4) & 1) * 16;
    const uint32_t bRow = (lane & 7) + ((lane >> 4) & 1) * 8;
    const uint32_t bK   = ((lane >> 3) & 1) * 16;

    load_stage(0, 0);

    for (int it = 0; it < 32; ++it){
        asm volatile("cp.async.wait_group 0;" ::: "memory");
        __syncthreads();
        if (it + 1 < 32) load_stage((it + 1) * 32, (it + 1) & 1);

        const uint32_t sbu = smBase + (it & 1) * STAGEB;
        #pragma unroll
        for (int ks = 0; ks < 2; ks++){
            uint32_t a0[2][4], a1[2][4];
            #pragma unroll
            for (int mt = 0; mt < 2; mt++){
                LDSM4(a0[mt], sbu + (wM*32 + mt*16 + aRow)*PITCH + ks*32 + aK);
                LDSM4(a1[mt], sbu + MATB + (wM*32 + mt*16 + aRow)*PITCH + ks*32 + aK);
            }
            #pragma unroll
            for (int ntp = 0; ntp < 4; ntp++){
                uint32_t bh[4], bl[4];
                uint32_t bro = (wN*64 + ntp*16 + bRow)*PITCH + ks*32 + bK;
                LDSM4(bh, sbu + 2*MATB + bro);
                LDSM4(bl, sbu + 3*MATB + bro);
                #pragma unroll
                for (int hf = 0; hf < 2; hf++)
                    #pragma unroll
                    for (int mt = 0; mt < 2; mt++)
                        MMA_BF16(c[mt][ntp*2+hf], a0[mt], bh[hf*2], bh[hf*2+1]);
                #pragma unroll
                for (int hf = 0; hf < 2; hf++)
                    #pragma unroll
                    for (int mt = 0; mt < 2; mt++)
                        MMA_BF16(c[mt][ntp*2+hf], a0[mt], bl[hf*2], bl[hf*2+1]);
                #pragma unroll
                for (int hf = 0; hf < 2; hf++)
                    #pragma unroll
                    for (int mt = 0; mt < 2; mt++)
                        MMA_BF16(c[mt][ntp*2+hf], a1[mt], bh[hf*2], bh[hf*2+1]);
            }
        }
    }

    // --- epilogue ---
    #pragma unroll
    for (int mt = 0; mt < 2; mt++){
        int row0 = rowBase + wM*32 + mt*16 + g;
        #pragma unroll
        for (int nt = 0; nt < 8; nt++){
            int col = colBase + wN*64 + nt*8 + t*2;
            float2 bz = *(const float2*)(bias + col);
            #pragma unroll
            for (int hrow = 0; hrow < 2; hrow++){
                int row = row0 + hrow*8;
                float vx = c[mt][nt][hrow*2]   + bz.x;
                float vy = c[mt][nt][hrow*2+1] + bz.y;
                if (isQ){
                    int b = row / NN, qi = row % NN;
                    int hh = col >> 6, d2 = col & 63;
                    uint32_t hi, lo;
                    split2(vx * SCALE_Q, vy * SCALE_Q, hi, lo);
                    size_t o = ((size_t)(b*HH + hh) * NN + qi) * DHH + d2;
                    *(uint32_t*)&g_qhi[o] = hi;
                    *(uint32_t*)&g_qlo[o] = lo;
                } else {
                    int b = row / LL, jj = row % LL;
                    if (col < DD){
                        int hh = col >> 6, d2 = col & 63;
                        size_t o = ((size_t)(b*HH + hh) * LL + jj) * DHH + d2;
                        *(uint32_t*)&g_khi[o] =
                            bpack(__float2bfloat16_rn(vx), __float2bfloat16_rn(vy));
                    } else {
                        int c2 = col - DD;
                        int hh = c2 >> 6, d2 = c2 & 63;
                        uint32_t hi, lo;
                        split2(vx, vy, hi, lo);
                        size_t o = ((size_t)(b*HH + hh) * LL + jj) * DHH + d2;
                        *(uint32_t*)&g_vhi[o] = hi;
                        *(uint32_t*)&g_vlo[o] = lo;
                    }
                }
            }
        }
    }
}

// O-projection: out = ao @ Wo + bo  (round-7 exact)
__global__ __launch_bounds__(256, 2) void gemm_o(const float* __restrict__ bias,
                                                 float* __restrict__ out)
{
    extern __shared__ char sm[];
    const int tid  = threadIdx.x;
    const int lane = tid & 31;
    const int warp = tid >> 5;
    const int wM = warp & 3, wN = warp >> 2;
    const int g  = lane >> 2, t = lane & 3;

    const int rowBase = blockIdx.y * 128;
    const int colBase = blockIdx.x * 128;

    int      lr[2];  uint32_t lcb[2];
    const char *pAh[2], *pAl[2], *pBh[2], *pBl[2];
    #pragma unroll
    for (int j = 0; j < 2; j++){
        int idx = tid + j * 256;
        lr[j]  = idx >> 2;
        lcb[j] = (idx & 3) * 16;
        size_t ro = (size_t)(rowBase + lr[j]) * DD;
        pAh[j] = (const char*)(g_aohi + ro);
        pAl[j] = (const char*)(g_aolo + ro);
        size_t bo = (size_t)(colBase + lr[j]) * DD;
        pBh[j] = (const char*)(g_wot_hi + bo);
        pBl[j] = (const char*)(g_wot_lo + bo);
    }

    const uint32_t smBase = s2u(sm);
    auto load_stage = [&](int k0, int stage){
        uint32_t sb = smBase + stage * STAGEB;
        #pragma unroll
        for (int j = 0; j < 2; j++){
            uint32_t so = lr[j] * PITCH + lcb[j];
            size_t   go = (size_t)k0 * 2 + lcb[j];
            cp16(sb + so,          pAh[j] + go);
            cp16(sb + MATB + so,   pAl[j] + go);
            cp16(sb + 2*MATB + so, pBh[j] + go);
            cp16(sb + 3*MATB + so, pBl[j] + go);
        }
        CP_COMMIT();
    };

    float c[2][8][4];
    #pragma unroll
    for (int mt = 0; mt < 2; mt++)
        #pragma unroll
        for (int nt = 0; nt < 8; nt++)
            #pragma unroll
            for (int i = 0; i < 4; i++) c[mt][nt][i] = 0.f;

    const uint32_t aRow = (lane & 7) + ((lane >> 3) & 1) * 8;
    const uint32_t aK   = ((lane >> 4) & 1) * 16;
    const uint32_t bRow = (lane & 7) + ((lane >> 4) & 1) * 8;
    const uint32_t bK   = ((lane >> 3) & 1) * 16;

    load_stage(0, 0);

    for (int it = 0; it < 32; ++it){
        asm volatile("cp.async.wait_group 0;" ::: "memory");
        __syncthreads();
        if (it + 1 < 32) load_stage((it + 1) * 32, (it + 1) & 1);

        const uint32_t sbu = smBase + (it & 1) * STAGEB;
        #pragma unroll
        for (int ks = 0; ks < 2; ks++){
            uint32_t a0[2][4], a1[2][4];
            #pragma unroll
            for (int mt = 0; mt < 2; mt++){
                LDSM4(a0[mt], sbu + (wM*32 + mt*16 + aRow)*PITCH + ks*32 + aK);
                LDSM4(a1[mt], sbu + MATB + (wM*32 + mt*16 + aRow)*PITCH + ks*32 + aK);
            }
            #pragma unroll
            for (int ntp = 0; ntp < 4; ntp++){
                uint32_t bh[4], bl[4];
                uint32_t bro = (wN*64 + ntp*16 + bRow)*PITCH + ks*32 + bK;
                LDSM4(bh, sbu + 2*MATB + bro);
                LDSM4(bl, sbu + 3*MATB + bro);
                #pragma unroll
                for (int hf = 0; hf < 2; hf++)
                    #pragma unroll
                    for (int mt = 0; mt < 2; mt++)
                        MMA_BF16(c[mt][ntp*2+hf], a0[mt], bh[hf*2], bh[hf*2+1]);
                #pragma unroll
                for (int hf = 0; hf < 2; hf++)
                    #pragma unroll
                    for (int mt = 0; mt < 2; mt++)
                        MMA_BF16(c[mt][ntp*2+hf], a0[mt], bl[hf*2], bl[hf*2+1]);
                #pragma unroll
                for (int hf = 0; hf < 2; hf++)
                    #pragma unroll
                    for (int mt = 0; mt < 2; mt++)
                        MMA_BF16(c[mt][ntp*2+hf], a1[mt], bh[hf*2], bh[hf*2+1]);
            }
        }
    }

    #pragma unroll
    for (int mt = 0; mt < 2; mt++){
        int row0 = rowBase + wM*32 + mt*16 + g;
        #pragma unroll
        for (int nt = 0; nt < 8; nt++){
            int col = colBase + wN*64 + nt*8 + t*2;
            float2 bz = *(const float2*)(bias + col);
            #pragma unroll
            for (int hrow = 0; hrow < 2; hrow++){
                int row = row0 + hrow*8;
                *(float2*)&out[(size_t)row * DD + col] =
                    make_float2(c[mt][nt][hrow*2] + bz.x, c[mt][nt][hrow*2+1] + bz.y);
            }
        }
    }
}

// ---------------------------------------------------------------------------
// HMMA flash attention, BALANCED-PAIR persistent: grid (8, 16, 2) = 256 CTAs.
// Each CTA processes q-blocks {15-i, i}: per-pair cost is constant (66 KV
// blocks), so the whole kernel is ONE perfectly balanced wave.
// Inner loops are round-10 exact: 64-key tiles, 2-stage ring, K bf16-hi only,
// PV 3-term split, ex2 softmax.
// ---------------------------------------------------------------------------
#define KROW    144
#define KVMAT   (64*KROW)
#define KVSTAGE (3*KVMAT)            // Khi, Vhi, Vlo = 27648 B
#define FA_SMEM (2*KVSTAGE)          // 55296 B

__global__ __launch_bounds__(256, 2) void flash_mma()
{
    extern __shared__ char fsm[];
    const int tid = threadIdx.x, lane = tid & 31, warp = tid >> 5;
    const int g = lane >> 2, t = lane & 3;
    const int h  = blockIdx.y;
    const int b  = blockIdx.z;

    const size_t kvbase = (size_t)(b*HH + h) * LL;
    const uint32_t fsb = s2u(fsm);

    const uint32_t kRowL = (lane & 7) + ((lane >> 4) & 1) * 8;
    const uint32_t kKL   = ((lane >> 3) & 1) * 16;
    const uint32_t rowad = (lane & 7)*KROW + ((lane >> 4) & 1)*16 +
                           (((lane >> 3) & 1) ? 8*KROW : 0);

    #pragma unroll 1
    for (int u = 0; u < 2; u++){
        // pair (15 - i, i): heavy unit first; total cost constant across CTAs
        const int qb = u == 0 ? (15 - (int)blockIdx.x) : (int)blockIdx.x;
        const int q0 = qb * 128;

        // --- Q fragments for this unit ---
        const __nv_bfloat16* qh = g_qhi + ((size_t)(b*HH + h) * NN + q0 + warp*16) * DHH;
        const __nv_bfloat16* ql = g_qlo + ((size_t)(b*HH + h) * NN + q0 + warp*16) * DHH;
        uint32_t qa[2][4][4];
        #pragma unroll
        for (int kc = 0; kc < 4; kc++){
            int e0 = g*DHH + kc*16 + 2*t;
            qa[0][kc][0] = *(const uint32_t*)(qh + e0);
            qa[0][kc][1] = *(const uint32_t*)(qh + e0 + 8*DHH);
            qa[0][kc][2] = *(const uint32_t*)(qh + e0 + 8);
            qa[0][kc][3] = *(const uint32_t*)(qh + e0 + 8*DHH + 8);
            qa[1][kc][0] = *(const uint32_t*)(ql + e0);
            qa[1][kc][1] = *(const uint32_t*)(ql + e0 + 8*DHH);
            qa[1][kc][2] = *(const uint32_t*)(ql + e0 + 8);
            qa[1][kc][3] = *(const uint32_t*)(ql + e0 + 8*DHH + 8);
        }

        float o[8][4];
        #pragma unroll
        for (int nt = 0; nt < 8; nt++)
            #pragma unroll
            for (int i = 0; i < 4; i++) o[nt][i] = 0.f;
        float m2[2] = {-1e30f, -1e30f}, l2[2] = {0.f, 0.f};

        const int nSelf = q0/64 + 2;
        const int nBlk  = nSelf + MM/64;
        auto jof = [&](int blk){ return blk < nSelf ? blk*64 : NN + (blk - nSelf)*64; };

        auto load_kv = [&](int j0, int st){
            uint32_t sb = fsb + st * KVSTAGE;
            size_t go = (kvbase + j0) * DHH;
            #pragma unroll
            for (int i = 0; i < 2; i++){
                int idx = tid + i*256;          // 0..511 = 64 rows x 8 chunks
                int r = idx >> 3, cb = (idx & 7) * 16;
                uint32_t so = r*KROW + cb;
                size_t ge = go + (size_t)r*DHH + (cb >> 1);
                cp16(sb + so,           g_khi + ge);
                cp16(sb + KVMAT + so,   g_vhi + ge);
                cp16(sb + 2*KVMAT + so, g_vlo + ge);
            }
            CP_COMMIT();
        };

        load_kv(0, 0);

        for (int blk = 0; blk < nBlk; ++blk){
            const int j0 = jof(blk);
            asm volatile("cp.async.wait_group 0;" ::: "memory");
            __syncthreads();
            if (blk + 1 < nBlk) load_kv(jof(blk + 1), (blk + 1) & 1);

            const uint32_t stU = fsb + (blk & 1) * KVSTAGE;
            const uint32_t KhU = stU;
            const uint32_t vhB = stU + KVMAT;
            const uint32_t vlB = stU + 2*KVMAT;

            // --- S = (qhi + qlo) · khi ---
            float s[8][4];
            #pragma unroll
            for (int nt = 0; nt < 8; nt++)
                s[nt][0] = s[nt][1] = s[nt][2] = s[nt][3] = 0.f;
            #pragma unroll
            for (int kc = 0; kc < 4; kc++){
                #pragma unroll
                for (int ntp = 0; ntp < 4; ntp++){
                    uint32_t bh[4];
                    LDSM4(bh, KhU + (ntp*16 + kRowL)*KROW + kc*32 + kKL);
                    MMA_BF16(s[ntp*2],   qa[0][kc], bh[0], bh[1]);
                    MMA_BF16(s[ntp*2+1], qa[0][kc], bh[2], bh[3]);
                    MMA_BF16(s[ntp*2],   qa[1][kc], bh[0], bh[1]);
                    MMA_BF16(s[ntp*2+1], qa[1][kc], bh[2], bh[3]);
                }
            }

            // --- causal mask (last two self tiles only) ---
            if (blk >= nSelf - 2 && blk < nSelf){
                int rA = q0 + warp*16 + g, rB = rA + 8;
                #pragma unroll
                for (int nt = 0; nt < 8; nt++){
                    int k0 = j0 + nt*8 + 2*t;
                    if (k0     > rA) s[nt][0] = -1e30f;
                    if (k0 + 1 > rA) s[nt][1] = -1e30f;
                    if (k0     > rB) s[nt][2] = -1e30f;
                    if (k0 + 1 > rB) s[nt][3] = -1e30f;
                }
            }

            // --- online softmax (exp2 domain) ---
            float mxA = -1e30f, mxB = -1e30f;
            #pragma unroll
            for (int nt = 0; nt < 8; nt++){
                mxA = fmaxf(mxA, fmaxf(s[nt][0], s[nt][1]));
                mxB = fmaxf(mxB, fmaxf(s[nt][2], s[nt][3]));
            }
            mxA = fmaxf(mxA, __shfl_xor_sync(0xffffffffu, mxA, 1));
            mxA = fmaxf(mxA, __shfl_xor_sync(0xffffffffu, mxA, 2));
            mxB = fmaxf(mxB, __shfl_xor_sync(0xffffffffu, mxB, 1));
            mxB = fmaxf(mxB, __shfl_xor_sync(0xffffffffu, mxB, 2));

            float mnA = fmaxf(m2[0], mxA), mnB = fmaxf(m2[1], mxB);
            float aA = ex2(m2[0] - mnA), aB = ex2(m2[1] - mnB);
            float sA = 0.f, sB = 0.f;
            #pragma unroll
            for (int nt = 0; nt < 8; nt++){
                s[nt][0] = ex2(s[nt][0] - mnA);
                s[nt][1] = ex2(s[nt][1] - mnA);
                s[nt][2] = ex2(s[nt][2] - mnB);
                s[nt][3] = ex2(s[nt][3] - mnB);
                sA += s[nt][0] + s[nt][1];
                sB += s[nt][2] + s[nt][3];
            }
            sA += __shfl_xor_sync(0xffffffffu, sA, 1);
            sA += __shfl_xor_sync(0xffffffffu, sA, 2);
            sB += __shfl_xor_sync(0xffffffffu, sB, 1);
            sB += __shfl_xor_sync(0xffffffffu, sB, 2);
            l2[0] = l2[0]*aA + sA;  m2[0] = mnA;
            l2[1] = l2[1]*aB + sB;  m2[1] = mnB;
            #pragma unroll
            for (int nt = 0; nt < 8; nt++){
                o[nt][0] *= aA; o[nt][1] *= aA;
                o[nt][2] *= aB; o[nt][3] *= aB;
            }

            // --- O += P V (split 3-MMA) ---
            #pragma unroll
            for (int kc = 0; kc < 4; kc++){
                const float* pa = s[2*kc];
                const float* pb = s[2*kc + 1];
                uint32_t Ahi[4], Alo[4];
                split2(pa[0], pa[1], Ahi[0], Alo[0]);
                split2(pa[2], pa[3], Ahi[1], Alo[1]);
                split2(pb[0], pb[1], Ahi[2], Alo[2]);
                split2(pb[2], pb[3], Ahi[3], Alo[3]);

                uint32_t base = kc*16*KROW + rowad;
                #pragma unroll
                for (int dn2 = 0; dn2 < 4; dn2++){
                    uint32_t bh0, bh1, bh2, bh3, bl0, bl1, bl2, bl3;
                    LDSM4T(bh0, bh1, bh2, bh3, vhB + base + dn2*32);
                    LDSM4T(bl0, bl1, bl2, bl3, vlB + base + dn2*32);
                    MMA_BF16(o[dn2*2],     Ahi, bh0, bh1);
                    MMA_BF16(o[dn2*2 + 1], Ahi, bh2, bh3);
                    MMA_BF16(o[dn2*2],     Ahi, bl0, bl1);
                    MMA_BF16(o[dn2*2 + 1], Ahi, bl2, bl3);
                    MMA_BF16(o[dn2*2],     Alo, bh0, bh1);
                    MMA_BF16(o[dn2*2 + 1], Alo, bh2, bh3);
                }
            }
        }

        // --- normalize + write split-bf16 ao [b, n, h*64+dh] ---
        float iA = 1.f / l2[0], iB = 1.f / l2[1];
        size_t rA = (size_t)b*NN + q0 + warp*16 + g;
        #pragma unroll
        for (int nt = 0; nt < 8; nt++){
            int col = h*64 + nt*8 + 2*t;
            uint32_t hi, lo;
            split2(o[nt][0]*iA, o[nt][1]*iA, hi, lo);
            *(uint32_t*)&g_aohi[rA*DD + col] = hi;
            *(uint32_t*)&g_aolo[rA*DD + col] = lo;
            split2(o[nt][2]*iB, o[nt][3]*iB, hi, lo);
            *(uint32_t*)&g_aohi[(rA + 8)*DD + col] = hi;
            *(uint32_t*)&g_aolo[(rA + 8)*DD + col] = lo;
        }

        // smem WAR guard before the next unit's first load_kv
        __syncthreads();
    }
}

// ---------------------------------------------------------------------------
extern "C" void kernel_launch(void* const* d_in, const int* in_sizes, int n_in,
                              void* d_out, int out_size)
{
    const float* x       = (const float*)d_in[0];
    const float* context = (const float*)d_in[1];
    const float* Wq      = (const float*)d_in[2];
    const float* bq      = (const float*)d_in[3];
    const float* Wkv     = (const float*)d_in[4];
    const float* bkv     = (const float*)d_in[5];
    const float* Wo      = (const float*)d_in[6];
    const float* bo      = (const float*)d_in[7];
    float* out = (float*)d_out;

    cudaFuncSetAttribute(gemm_qkv,  cudaFuncAttributeMaxDynamicSharedMemorySize, GEMM_SMEM);
    cudaFuncSetAttribute(gemm_o,    cudaFuncAttributeMaxDynamicSharedMemorySize, GEMM_SMEM);
    cudaFuncSetAttribute(flash_mma, cudaFuncAttributeMaxDynamicSharedMemorySize, FA_SMEM);

    prep_all<<<NSPLIT_BLK + NTRANS_BLK, 256>>>(
        (const float4*)x, (const float4*)context, Wq, Wkv, Wo);

    gemm_qkv<<<1024, 256, GEMM_SMEM>>>(bq, bkv);
    flash_mma<<<dim3(NN/256, HH, BB), 256, FA_SMEM>>>();
    gemm_o<<<dim3(DD/128, (BB*NN)/128), 256, GEMM_SMEM>>>(bo, out);
}

// round 15
// speedup vs baseline: 1.1495x; 1.0258x over previous
#include <cuda_runtime.h>
#include <cuda_bf16.h>
#include <math.h>
#include <stdint.h>

// Problem constants
#define BB  2
#define NN  2048
#define MM  1024
#define LL  3072   // NN + MM
#define DD  1024
#define HH  16
#define DHH 64

#define SCALE_Q 0.18033688011112042f   // 0.125 * log2(e): softmax in exp2 domain

// ---------------------------------------------------------------------------
// Scratch (allocation-free rule: __device__ globals)
// K kept as bf16-hi ONLY (q·klo residual measured at ~6e-4 final rel err).
// ---------------------------------------------------------------------------
__device__ __align__(16) __nv_bfloat16 g_qhi[BB*HH*NN*DHH], g_qlo[BB*HH*NN*DHH];
__device__ __align__(16) __nv_bfloat16 g_khi[BB*HH*LL*DHH];
__device__ __align__(16) __nv_bfloat16 g_vhi[BB*HH*LL*DHH], g_vlo[BB*HH*LL*DHH];

__device__ __align__(16) __nv_bfloat16 g_xhi [BB*NN*DD], g_xlo [BB*NN*DD];
__device__ __align__(16) __nv_bfloat16 g_chi [BB*MM*DD], g_clo [BB*MM*DD];
__device__ __align__(16) __nv_bfloat16 g_wqt_hi [DD*DD],   g_wqt_lo [DD*DD];   // [n][k]
__device__ __align__(16) __nv_bfloat16 g_wkvt_hi[2*DD*DD], g_wkvt_lo[2*DD*DD]; // [n][k]
__device__ __align__(16) __nv_bfloat16 g_wot_hi [DD*DD],   g_wot_lo [DD*DD];   // [n][k]
__device__ __align__(16) __nv_bfloat16 g_aohi[BB*NN*DD], g_aolo[BB*NN*DD];

// ---------------------------------------------------------------------------
// Helpers
// ---------------------------------------------------------------------------
__device__ __forceinline__ uint32_t s2u(const void* p){
    uint32_t a;
    asm("{ .reg .u64 t; cvta.to.shared.u64 t, %1; cvt.u32.u64 %0, t; }" : "=r"(a) : "l"(p));
    return a;
}
__device__ __forceinline__ uint32_t bpack(__nv_bfloat16 a, __nv_bfloat16 b){
    return (uint32_t)__bfloat16_as_ushort(a) | ((uint32_t)__bfloat16_as_ushort(b) << 16);
}
__device__ __forceinline__ void cp16(uint32_t s, const void* g){
    asm volatile("cp.async.cg.shared.global [%0], [%1], 16;" :: "r"(s), "l"(g));
}
#define CP_COMMIT() asm volatile("cp.async.commit_group;")

__device__ __forceinline__ float ex2(float x){
    float y; asm("ex2.approx.f32 %0, %1;" : "=f"(y) : "f"(x)); return y;
}

#define MMA_BF16(C, A, b0, b1) \
    asm volatile("mma.sync.aligned.m16n8k16.row.col.f32.bf16.bf16.f32 " \
        "{%0,%1,%2,%3}, {%4,%5,%6,%7}, {%8,%9}, {%0,%1,%2,%3};" \
        : "+f"((C)[0]), "+f"((C)[1]), "+f"((C)[2]), "+f"((C)[3]) \
        : "r"((A)[0]), "r"((A)[1]), "r"((A)[2]), "r"((A)[3]), "r"(b0), "r"(b1))

#define LDSM4(r, addr) \
    asm volatile("ldmatrix.sync.aligned.m8n8.x4.shared.b16 {%0,%1,%2,%3}, [%4];" \
        : "=r"((r)[0]), "=r"((r)[1]), "=r"((r)[2]), "=r"((r)[3]) : "r"(addr))

#define LDSM4T(r0,r1,r2,r3,addr) \
    asm volatile("ldmatrix.sync.aligned.m8n8.x4.trans.shared.b16 {%0,%1,%2,%3}, [%4];" \
        : "=r"(r0), "=r"(r1), "=r"(r2), "=r"(r3) : "r"(addr))

__device__ __forceinline__ void split2(float x, float y, uint32_t& hi, uint32_t& lo){
    __nv_bfloat16 h0 = __float2bfloat16_rn(x), h1 = __float2bfloat16_rn(y);
    hi = bpack(h0, h1);
    lo = bpack(__float2bfloat16_rn(x - __bfloat162float(h0)),
               __float2bfloat16_rn(y - __bfloat162float(h1)));
}

// ---------------------------------------------------------------------------
// Prep: ONE kernel — splits x/context AND transposes+splits all weights.
// ---------------------------------------------------------------------------
#define NX4 (BB*NN*DD/4)
#define NC4 (BB*MM*DD/4)
#define NSPLIT_BLK ((NX4 + NC4) / 256)        // 6144
#define NTRANS_BLK (128 * 32)                 // 4096

__global__ __launch_bounds__(256) void prep_all(
    const float4* __restrict__ x, const float4* __restrict__ ctx,
    const float* __restrict__ Wq, const float* __restrict__ Wkv,
    const float* __restrict__ Wo)
{
    int bid = blockIdx.x;
    if (bid < NSPLIT_BLK){
        int i = bid * 256 + threadIdx.x;
        const float4* src;  uint2 *hi, *lo;  int j;
        if (i < NX4){ src = x;   hi = (uint2*)g_xhi; lo = (uint2*)g_xlo; j = i; }
        else        { src = ctx; hi = (uint2*)g_chi; lo = (uint2*)g_clo; j = i - NX4; }
        float4 v = src[j];
        uint32_t h0, l0, h1, l1;
        split2(v.x, v.y, h0, l0);
        split2(v.z, v.w, h1, l1);
        hi[j] = make_uint2(h0, h1);
        lo[j] = make_uint2(l0, l1);
        return;
    }
    int id = bid - NSPLIT_BLK;
    int cx = id & 127, ky = id >> 7;
    const float* W; __nv_bfloat16 *th, *tl; int N, n0;
    if (cx < 32){       W = Wq;  N = 1024; n0 = cx*32;      th = g_wqt_hi;  tl = g_wqt_lo;  }
    else if (cx < 96){  W = Wkv; N = 2048; n0 = (cx-32)*32; th = g_wkvt_hi; tl = g_wkvt_lo; }
    else{               W = Wo;  N = 1024; n0 = (cx-96)*32; th = g_wot_hi;  tl = g_wot_lo;  }

    __shared__ float t[32][33];
    int k0 = ky * 32;
    int tx = threadIdx.x & 31, ty = threadIdx.x >> 5;
    #pragma unroll
    for (int r = 0; r < 4; r++)
        t[ty + r*8][tx] = W[(size_t)(k0 + ty + r*8) * N + n0 + tx];
    __syncthreads();
    #pragma unroll
    for (int r = 0; r < 4; r++){
        int n = ty + r*8;
        float v = t[tx][n];
        __nv_bfloat16 h = __float2bfloat16_rn(v);
        __nv_bfloat16 l = __float2bfloat16_rn(v - __bfloat162float(h));
        size_t o = (size_t)(n0 + n) * 1024 + k0 + tx;
        th[o] = h; tl[o] = l;
    }
}

// ---------------------------------------------------------------------------
// Shared GEMM machinery: 128x128 CTA tile, BK=32, double-buffered cp.async,
// one __syncthreads per K-iter, product-major MMA ordering. (round-7 exact;
// proven local optimum, frozen)
// ---------------------------------------------------------------------------
#define PITCH 80
#define MATB  (128*PITCH)
#define STAGEB (4*MATB)
#define GEMM_SMEM (2*STAGEB)

// Fused Q + KV projection: 1024 CTAs. cid<256 -> Q tile; else KV tile.
__global__ __launch_bounds__(256, 2) void gemm_qkv(const float* __restrict__ bq,
                                                   const float* __restrict__ bkv)
{
    extern __shared__ char sm[];
    const int tid  = threadIdx.x;
    const int lane = tid & 31;
    const int warp = tid >> 5;
    const int wM = warp & 3, wN = warp >> 2;
    const int g  = lane >> 2, t = lane & 3;

    const int cid = blockIdx.x;
    const bool isQ = (cid < 256);
    int rowBase, colBase;
    const __nv_bfloat16 *Bh, *Bl;
    const float* bias;
    if (isQ){
        rowBase = (cid >> 3) * 128;  colBase = (cid & 7) * 128;
        Bh = g_wqt_hi;  Bl = g_wqt_lo;  bias = bq;
    } else {
        int c2 = cid - 256;
        rowBase = (c2 >> 4) * 128;   colBase = (c2 & 15) * 128;
        Bh = g_wkvt_hi; Bl = g_wkvt_lo; bias = bkv;
    }

    int      lr[2];  uint32_t lcb[2];
    const char *pAh[2], *pAl[2], *pBh[2], *pBl[2];
    #pragma unroll
    for (int j = 0; j < 2; j++){
        int idx = tid + j * 256;
        lr[j]  = idx >> 2;
        lcb[j] = (idx & 3) * 16;
        int row = rowBase + lr[j];
        const __nv_bfloat16 *ah, *al; size_t ro;
        if (isQ){
            ah = g_xhi;  al = g_xlo;  ro = (size_t)row * DD;
        } else {
            int b = row / LL, jj = row % LL;
            if (jj < NN){ ah = g_xhi; al = g_xlo; ro = (size_t)(b*NN + jj) * DD; }
            else        { ah = g_chi; al = g_clo; ro = (size_t)(b*MM + jj - NN) * DD; }
        }
        pAh[j] = (const char*)(ah + ro);
        pAl[j] = (const char*)(al + ro);
        size_t bo = (size_t)(colBase + lr[j]) * DD;
        pBh[j] = (const char*)(Bh + bo);
        pBl[j] = (const char*)(Bl + bo);
    }

    const uint32_t smBase = s2u(sm);
    auto load_stage = [&](int k0, int stage){
        uint32_t sb = smBase + stage * STAGEB;
        #pragma unroll
        for (int j = 0; j < 2; j++){
            uint32_t so = lr[j] * PITCH + lcb[j];
            size_t   go = (size_t)k0 * 2 + lcb[j];
            cp16(sb + so,          pAh[j] + go);
            cp16(sb + MATB + so,   pAl[j] + go);
            cp16(sb + 2*MATB + so, pBh[j] + go);
            cp16(sb + 3*MATB + so, pBl[j] + go);
        }
        CP_COMMIT();
    };

    float c[2][8][4];
    #pragma unroll
    for (int mt = 0; mt < 2; mt++)
        #pragma unroll
        for (int nt = 0; nt < 8; nt++)
            #pragma unroll
            for (int i = 0; i < 4; i++) c[mt][nt][i] = 0.f;

    const uint32_t aRow = (lane & 7) + ((lane >> 3) & 1) * 8;
    const uint32_t aK   = ((lane >> 4) & 1) * 16;
    const uint32_t bRow = (lane & 7) + ((lane >> 4) & 1) * 8;
    const uint32_t bK   = ((lane >> 3) & 1) * 16;

    load_stage(0, 0);

    for (int it = 0; it < 32; ++it){
        asm volatile("cp.async.wait_group 0;" ::: "memory");
        __syncthreads();
        if (it + 1 < 32) load_stage((it + 1) * 32, (it + 1) & 1);

        const uint32_t sbu = smBase + (it & 1) * STAGEB;
        #pragma unroll
        for (int ks = 0; ks < 2; ks++){
            uint32_t a0[2][4], a1[2][4];
            #pragma unroll
            for (int mt = 0; mt < 2; mt++){
                LDSM4(a0[mt], sbu + (wM*32 + mt*16 + aRow)*PITCH + ks*32 + aK);
                LDSM4(a1[mt], sbu + MATB + (wM*32 + mt*16 + aRow)*PITCH + ks*32 + aK);
            }
            #pragma unroll
            for (int ntp = 0; ntp < 4; ntp++){
                uint32_t bh[4], bl[4];
                uint32_t bro = (wN*64 + ntp*16 + bRow)*PITCH + ks*32 + bK;
                LDSM4(bh, sbu + 2*MATB + bro);
                LDSM4(bl, sbu + 3*MATB + bro);
                #pragma unroll
                for (int hf = 0; hf < 2; hf++)
                    #pragma unroll
                    for (int mt = 0; mt < 2; mt++)
                        MMA_BF16(c[mt][ntp*2+hf], a0[mt], bh[hf*2], bh[hf*2+1]);
                #pragma unroll
                for (int hf = 0; hf < 2; hf++)
                    #pragma unroll
                    for (int mt = 0; mt < 2; mt++)
                        MMA_BF16(c[mt][ntp*2+hf], a0[mt], bl[hf*2], bl[hf*2+1]);
                #pragma unroll
                for (int hf = 0; hf < 2; hf++)
                    #pragma unroll
                    for (int mt = 0; mt < 2; mt++)
                        MMA_BF16(c[mt][ntp*2+hf], a1[mt], bh[hf*2], bh[hf*2+1]);
            }
        }
    }

    // --- epilogue ---
    #pragma unroll
    for (int mt = 0; mt < 2; mt++){
        int row0 = rowBase + wM*32 + mt*16 + g;
        #pragma unroll
        for (int nt = 0; nt < 8; nt++){
            int col = colBase + wN*64 + nt*8 + t*2;
            float2 bz = *(const float2*)(bias + col);
            #pragma unroll
            for (int hrow = 0; hrow < 2; hrow++){
                int row = row0 + hrow*8;
                float vx = c[mt][nt][hrow*2]   + bz.x;
                float vy = c[mt][nt][hrow*2+1] + bz.y;
                if (isQ){
                    int b = row / NN, qi = row % NN;
                    int hh = col >> 6, d2 = col & 63;
                    uint32_t hi, lo;
                    split2(vx * SCALE_Q, vy * SCALE_Q, hi, lo);
                    size_t o = ((size_t)(b*HH + hh) * NN + qi) * DHH + d2;
                    *(uint32_t*)&g_qhi[o] = hi;
                    *(uint32_t*)&g_qlo[o] = lo;
                } else {
                    int b = row / LL, jj = row % LL;
                    if (col < DD){
                        int hh = col >> 6, d2 = col & 63;
                        size_t o = ((size_t)(b*HH + hh) * LL + jj) * DHH + d2;
                        *(uint32_t*)&g_khi[o] =
                            bpack(__float2bfloat16_rn(vx), __float2bfloat16_rn(vy));
                    } else {
                        int c2 = col - DD;
                        int hh = c2 >> 6, d2 = c2 & 63;
                        uint32_t hi, lo;
                        split2(vx, vy, hi, lo);
                        size_t o = ((size_t)(b*HH + hh) * LL + jj) * DHH + d2;
                        *(uint32_t*)&g_vhi[o] = hi;
                        *(uint32_t*)&g_vlo[o] = lo;
                    }
                }
            }
        }
    }
}

// O-projection: out = ao @ Wo + bo  (round-7 exact)
__global__ __launch_bounds__(256, 2) void gemm_o(const float* __restrict__ bias,
                                                 float* __restrict__ out)
{
    extern __shared__ char sm[];
    const int tid  = threadIdx.x;
    const int lane = tid & 31;
    const int warp = tid >> 5;
    const int wM = warp & 3, wN = warp >> 2;
    const int g  = lane >> 2, t = lane & 3;

    const int rowBase = blockIdx.y * 128;
    const int colBase = blockIdx.x * 128;

    int      lr[2];  uint32_t lcb[2];
    const char *pAh[2], *pAl[2], *pBh[2], *pBl[2];
    #pragma unroll
    for (int j = 0; j < 2; j++){
        int idx = tid + j * 256;
        lr[j]  = idx >> 2;
        lcb[j] = (idx & 3) * 16;
        size_t ro = (size_t)(rowBase + lr[j]) * DD;
        pAh[j] = (const char*)(g_aohi + ro);
        pAl[j] = (const char*)(g_aolo + ro);
        size_t bo = (size_t)(colBase + lr[j]) * DD;
        pBh[j] = (const char*)(g_wot_hi + bo);
        pBl[j] = (const char*)(g_wot_lo + bo);
    }

    const uint32_t smBase = s2u(sm);
    auto load_stage = [&](int k0, int stage){
        uint32_t sb = smBase + stage * STAGEB;
        #pragma unroll
        for (int j = 0; j < 2; j++){
            uint32_t so = lr[j] * PITCH + lcb[j];
            size_t   go = (size_t)k0 * 2 + lcb[j];
            cp16(sb + so,          pAh[j] + go);
            cp16(sb + MATB + so,   pAl[j] + go);
            cp16(sb + 2*MATB + so, pBh[j] + go);
            cp16(sb + 3*MATB + so, pBl[j] + go);
        }
        CP_COMMIT();
    };

    float c[2][8][4];
    #pragma unroll
    for (int mt = 0; mt < 2; mt++)
        #pragma unroll
        for (int nt = 0; nt < 8; nt++)
            #pragma unroll
            for (int i = 0; i < 4; i++) c[mt][nt][i] = 0.f;

    const uint32_t aRow = (lane & 7) + ((lane >> 3) & 1) * 8;
    const uint32_t aK   = ((lane >> 4) & 1) * 16;
    const uint32_t bRow = (lane & 7) + ((lane >> 4) & 1) * 8;
    const uint32_t bK   = ((lane >> 3) & 1) * 16;

    load_stage(0, 0);

    for (int it = 0; it < 32; ++it){
        asm volatile("cp.async.wait_group 0;" ::: "memory");
        __syncthreads();
        if (it + 1 < 32) load_stage((it + 1) * 32, (it + 1) & 1);

        const uint32_t sbu = smBase + (it & 1) * STAGEB;
        #pragma unroll
        for (int ks = 0; ks < 2; ks++){
            uint32_t a0[2][4], a1[2][4];
            #pragma unroll
            for (int mt = 0; mt < 2; mt++){
                LDSM4(a0[mt], sbu + (wM*32 + mt*16 + aRow)*PITCH + ks*32 + aK);
                LDSM4(a1[mt], sbu + MATB + (wM*32 + mt*16 + aRow)*PITCH + ks*32 + aK);
            }
            #pragma unroll
            for (int ntp = 0; ntp < 4; ntp++){
                uint32_t bh[4], bl[4];
                uint32_t bro = (wN*64 + ntp*16 + bRow)*PITCH + ks*32 + bK;
                LDSM4(bh, sbu + 2*MATB + bro);
                LDSM4(bl, sbu + 3*MATB + bro);
                #pragma unroll
                for (int hf = 0; hf < 2; hf++)
                    #pragma unroll
                    for (int mt = 0; mt < 2; mt++)
                        MMA_BF16(c[mt][ntp*2+hf], a0[mt], bh[hf*2], bh[hf*2+1]);
                #pragma unroll
                for (int hf = 0; hf < 2; hf++)
                    #pragma unroll
                    for (int mt = 0; mt < 2; mt++)
                        MMA_BF16(c[mt][ntp*2+hf], a0[mt], bl[hf*2], bl[hf*2+1]);
                #pragma unroll
                for (int hf = 0; hf < 2; hf++)
                    #pragma unroll
                    for (int mt = 0; mt < 2; mt++)
                        MMA_BF16(c[mt][ntp*2+hf], a1[mt], bh[hf*2], bh[hf*2+1]);
            }
        }
    }

    #pragma unroll
    for (int mt = 0; mt < 2; mt++){
        int row0 = rowBase + wM*32 + mt*16 + g;
        #pragma unroll
        for (int nt = 0; nt < 8; nt++){
            int col = colBase + wN*64 + nt*8 + t*2;
            float2 bz = *(const float2*)(bias + col);
            #pragma unroll
            for (int hrow = 0; hrow < 2; hrow++){
                int row = row0 + hrow*8;
                *(float2*)&out[(size_t)row * DD + col] =
                    make_float2(c[mt][nt][hrow*2] + bz.x, c[mt][nt][hrow*2+1] + bz.y);
            }
        }
    }
}

// ---------------------------------------------------------------------------
// HMMA flash attention, 9-BIN balanced schedule: grid (9, 16, 2) = 288 CTAs.
// Per (b,h) column: slot 0 -> {qb15}(48), slot 1 -> {qb14}(46),
// slot s in [2,8] -> {qb 15-s, qb s-2} (cost 62). Max bin 62 vs 66 before.
// Unit processing is round-14 exact (bit-identical numerics).
// ---------------------------------------------------------------------------
#define KROW    144
#define KVMAT   (64*KROW)
#define KVSTAGE (3*KVMAT)            // Khi, Vhi, Vlo = 27648 B
#define FA_SMEM (2*KVSTAGE)          // 55296 B

__global__ __launch_bounds__(256, 2) void flash_mma()
{
    extern __shared__ char fsm[];
    const int tid = threadIdx.x, lane = tid & 31, warp = tid >> 5;
    const int g = lane >> 2, t = lane & 3;
    const int slot = blockIdx.x;     // 0..8
    const int h  = blockIdx.y;
    const int b  = blockIdx.z;

    const size_t kvbase = (size_t)(b*HH + h) * LL;
    const uint32_t fsb = s2u(fsm);

    const uint32_t kRowL = (lane & 7) + ((lane >> 4) & 1) * 8;
    const uint32_t kKL   = ((lane >> 3) & 1) * 16;
    const uint32_t rowad = (lane & 7)*KROW + ((lane >> 4) & 1)*16 +
                           (((lane >> 3) & 1) ? 8*KROW : 0);

    const int nUnits = (slot < 2) ? 1 : 2;

    #pragma unroll 1
    for (int u = 0; u < nUnits; u++){
        int qb;
        if (slot == 0)      qb = 15;
        else if (slot == 1) qb = 14;
        else                qb = (u == 0) ? (15 - slot) : (slot - 2);  // heavy first
        const int q0 = qb * 128;

        // --- Q fragments for this unit ---
        const __nv_bfloat16* qh = g_qhi + ((size_t)(b*HH + h) * NN + q0 + warp*16) * DHH;
        const __nv_bfloat16* ql = g_qlo + ((size_t)(b*HH + h) * NN + q0 + warp*16) * DHH;
        uint32_t qa[2][4][4];
        #pragma unroll
        for (int kc = 0; kc < 4; kc++){
            int e0 = g*DHH + kc*16 + 2*t;
            qa[0][kc][0] = *(const uint32_t*)(qh + e0);
            qa[0][kc][1] = *(const uint32_t*)(qh + e0 + 8*DHH);
            qa[0][kc][2] = *(const uint32_t*)(qh + e0 + 8);
            qa[0][kc][3] = *(const uint32_t*)(qh + e0 + 8*DHH + 8);
            qa[1][kc][0] = *(const uint32_t*)(ql + e0);
            qa[1][kc][1] = *(const uint32_t*)(ql + e0 + 8*DHH);
            qa[1][kc][2] = *(const uint32_t*)(ql + e0 + 8);
            qa[1][kc][3] = *(const uint32_t*)(ql + e0 + 8*DHH + 8);
        }

        float o[8][4];
        #pragma unroll
        for (int nt = 0; nt < 8; nt++)
            #pragma unroll
            for (int i = 0; i < 4; i++) o[nt][i] = 0.f;
        float m2[2] = {-1e30f, -1e30f}, l2[2] = {0.f, 0.f};

        const int nSelf = q0/64 + 2;
        const int nBlk  = nSelf + MM/64;
        auto jof = [&](int blk){ return blk < nSelf ? blk*64 : NN + (blk - nSelf)*64; };

        auto load_kv = [&](int j0, int st){
            uint32_t sb = fsb + st * KVSTAGE;
            size_t go = (kvbase + j0) * DHH;
            #pragma unroll
            for (int i = 0; i < 2; i++){
                int idx = tid + i*256;          // 0..511 = 64 rows x 8 chunks
                int r = idx >> 3, cb = (idx & 7) * 16;
                uint32_t so = r*KROW + cb;
                size_t ge = go + (size_t)r*DHH + (cb >> 1);
                cp16(sb + so,           g_khi + ge);
                cp16(sb + KVMAT + so,   g_vhi + ge);
                cp16(sb + 2*KVMAT + so, g_vlo + ge);
            }
            CP_COMMIT();
        };

        load_kv(0, 0);

        for (int blk = 0; blk < nBlk; ++blk){
            const int j0 = jof(blk);
            asm volatile("cp.async.wait_group 0;" ::: "memory");
            __syncthreads();
            if (blk + 1 < nBlk) load_kv(jof(blk + 1), (blk + 1) & 1);

            const uint32_t stU = fsb + (blk & 1) * KVSTAGE;
            const uint32_t KhU = stU;
            const uint32_t vhB = stU + KVMAT;
            const uint32_t vlB = stU + 2*KVMAT;

            // --- S = (qhi + qlo) · khi ---
            float s[8][4];
            #pragma unroll
            for (int nt = 0; nt < 8; nt++)
                s[nt][0] = s[nt][1] = s[nt][2] = s[nt][3] = 0.f;
            #pragma unroll
            for (int kc = 0; kc < 4; kc++){
                #pragma unroll
                for (int ntp = 0; ntp < 4; ntp++){
                    uint32_t bh[4];
                    LDSM4(bh, KhU + (ntp*16 + kRowL)*KROW + kc*32 + kKL);
                    MMA_BF16(s[ntp*2],   qa[0][kc], bh[0], bh[1]);
                    MMA_BF16(s[ntp*2+1], qa[0][kc], bh[2], bh[3]);
                    MMA_BF16(s[ntp*2],   qa[1][kc], bh[0], bh[1]);
                    MMA_BF16(s[ntp*2+1], qa[1][kc], bh[2], bh[3]);
                }
            }

            // --- causal mask (last two self tiles only) ---
            if (blk >= nSelf - 2 && blk < nSelf){
                int rA = q0 + warp*16 + g, rB = rA + 8;
                #pragma unroll
                for (int nt = 0; nt < 8; nt++){
                    int k0 = j0 + nt*8 + 2*t;
                    if (k0     > rA) s[nt][0] = -1e30f;
                    if (k0 + 1 > rA) s[nt][1] = -1e30f;
                    if (k0     > rB) s[nt][2] = -1e30f;
                    if (k0 + 1 > rB) s[nt][3] = -1e30f;
                }
            }

            // --- online softmax (exp2 domain) ---
            float mxA = -1e30f, mxB = -1e30f;
            #pragma unroll
            for (int nt = 0; nt < 8; nt++){
                mxA = fmaxf(mxA, fmaxf(s[nt][0], s[nt][1]));
                mxB = fmaxf(mxB, fmaxf(s[nt][2], s[nt][3]));
            }
            mxA = fmaxf(mxA, __shfl_xor_sync(0xffffffffu, mxA, 1));
            mxA = fmaxf(mxA, __shfl_xor_sync(0xffffffffu, mxA, 2));
            mxB = fmaxf(mxB, __shfl_xor_sync(0xffffffffu, mxB, 1));
            mxB = fmaxf(mxB, __shfl_xor_sync(0xffffffffu, mxB, 2));

            float mnA = fmaxf(m2[0], mxA), mnB = fmaxf(m2[1], mxB);
            float aA = ex2(m2[0] - mnA), aB = ex2(m2[1] - mnB);
            float sA = 0.f, sB = 0.f;
            #pragma unroll
            for (int nt = 0; nt < 8; nt++){
                s[nt][0] = ex2(s[nt][0] - mnA);
                s[nt][1] = ex2(s[nt][1] - mnA);
                s[nt][2] = ex2(s[nt][2] - mnB);
                s[nt][3] = ex2(s[nt][3] - mnB);
                sA += s[nt][0] + s[nt][1];
                sB += s[nt][2] + s[nt][3];
            }
            sA += __shfl_xor_sync(0xffffffffu, sA, 1);
            sA += __shfl_xor_sync(0xffffffffu, sA, 2);
            sB += __shfl_xor_sync(0xffffffffu, sB, 1);
            sB += __shfl_xor_sync(0xffffffffu, sB, 2);
            l2[0] = l2[0]*aA + sA;  m2[0] = mnA;
            l2[1] = l2[1]*aB + sB;  m2[1] = mnB;
            #pragma unroll
            for (int nt = 0; nt < 8; nt++){
                o[nt][0] *= aA; o[nt][1] *= aA;
                o[nt][2] *= aB; o[nt][3] *= aB;
            }

            // --- O += P V (split 3-MMA) ---
            #pragma unroll
            for (int kc = 0; kc < 4; kc++){
                const float* pa = s[2*kc];
                const float* pb = s[2*kc + 1];
                uint32_t Ahi[4], Alo[4];
                split2(pa[0], pa[1], Ahi[0], Alo[0]);
                split2(pa[2], pa[3], Ahi[1], Alo[1]);
                split2(pb[0], pb[1], Ahi[2], Alo[2]);
                split2(pb[2], pb[3], Ahi[3], Alo[3]);

                uint32_t base = kc*16*KROW + rowad;
                #pragma unroll
                for (int dn2 = 0; dn2 < 4; dn2++){
                    uint32_t bh0, bh1, bh2, bh3, bl0, bl1, bl2, bl3;
                    LDSM4T(bh0, bh1, bh2, bh3, vhB + base + dn2*32);
                    LDSM4T(bl0, bl1, bl2, bl3, vlB + base + dn2*32);
                    MMA_BF16(o[dn2*2],     Ahi, bh0, bh1);
                    MMA_BF16(o[dn2*2 + 1], Ahi, bh2, bh3);
                    MMA_BF16(o[dn2*2],     Ahi, bl0, bl1);
                    MMA_BF16(o[dn2*2 + 1], Ahi, bl2, bl3);
                    MMA_BF16(o[dn2*2],     Alo, bh0, bh1);
                    MMA_BF16(o[dn2*2 + 1], Alo, bh2, bh3);
                }
            }
        }

        // --- normalize + write split-bf16 ao [b, n, h*64+dh] ---
        float iA = 1.f / l2[0], iB = 1.f / l2[1];
        size_t rA = (size_t)b*NN + q0 + warp*16 + g;
        #pragma unroll
        for (int nt = 0; nt < 8; nt++){
            int col = h*64 + nt*8 + 2*t;
            uint32_t hi, lo;
            split2(o[nt][0]*iA, o[nt][1]*iA, hi, lo);
            *(uint32_t*)&g_aohi[rA*DD + col] = hi;
            *(uint32_t*)&g_aolo[rA*DD + col] = lo;
            split2(o[nt][2]*iB, o[nt][3]*iB, hi, lo);
            *(uint32_t*)&g_aohi[(rA + 8)*DD + col] = hi;
            *(uint32_t*)&g_aolo[(rA + 8)*DD + col] = lo;
        }

        // smem WAR guard before the next unit's first load_kv
        __syncthreads();
    }
}

// ---------------------------------------------------------------------------
extern "C" void kernel_launch(void* const* d_in, const int* in_sizes, int n_in,
                              void* d_out, int out_size)
{
    const float* x       = (const float*)d_in[0];
    const float* context = (const float*)d_in[1];
    const float* Wq      = (const float*)d_in[2];
    const float* bq      = (const float*)d_in[3];
    const float* Wkv     = (const float*)d_in[4];
    const float* bkv     = (const float*)d_in[5];
    const float* Wo      = (const float*)d_in[6];
    const float* bo      = (const float*)d_in[7];
    float* out = (float*)d_out;

    cudaFuncSetAttribute(gemm_qkv,  cudaFuncAttributeMaxDynamicSharedMemorySize, GEMM_SMEM);
    cudaFuncSetAttribute(gemm_o,    cudaFuncAttributeMaxDynamicSharedMemorySize, GEMM_SMEM);
    cudaFuncSetAttribute(flash_mma, cudaFuncAttributeMaxDynamicSharedMemorySize, FA_SMEM);

    prep_all<<<NSPLIT_BLK + NTRANS_BLK, 256>>>(
        (const float4*)x, (const float4*)context, Wq, Wkv, Wo);

    gemm_qkv<<<1024, 256, GEMM_SMEM>>>(bq, bkv);
    flash_mma<<<dim3(9, HH, BB), 256, FA_SMEM>>>();
    gemm_o<<<dim3(DD/128, (BB*NN)/128), 256, GEMM_SMEM>>>(bo, out);
}